// round 15
// baseline (speedup 1.0000x reference)
#include <cuda_runtime.h>
#include <cuda_bf16.h>
#include <math.h>
#include <stdint.h>

#define BB 8
#define TT 2048
#define EE 512
#define CC 128
#define NCH 16
#define EPSV 1e-3f
#define INV_SQRT_E 0.04419417382415922f  // 512^-0.5

// ---------------------------------------------------------------------------
// scratch (device globals; no cudaMalloc allowed)
// ---------------------------------------------------------------------------
static __device__ float g_q[(size_t)BB * TT * EE];   // fp32 q (pre-softmax)

static __device__ __nv_bfloat16 xT_hi[(size_t)BB * TT * EE];
static __device__ __nv_bfloat16 xT_lo[(size_t)BB * TT * EE];
static __device__ __nv_bfloat16 w_hi[(size_t)4 * EE * EE];  // q,k,v,o
static __device__ __nv_bfloat16 w_lo[(size_t)4 * EE * EE];
static __device__ __nv_bfloat16 q_hi[(size_t)BB * TT * EE];
static __device__ __nv_bfloat16 q_lo[(size_t)BB * TT * EE];
static __device__ __nv_bfloat16 k_hi[(size_t)BB * TT * EE];
static __device__ __nv_bfloat16 k_lo[(size_t)BB * TT * EE];
static __device__ __nv_bfloat16 kT_hi[(size_t)BB * EE * TT];
static __device__ __nv_bfloat16 kT_lo[(size_t)BB * EE * TT];
static __device__ __nv_bfloat16 vT_hi[(size_t)BB * EE * TT];
static __device__ __nv_bfloat16 vT_lo[(size_t)BB * EE * TT];
static __device__ __nv_bfloat16 S_hi[(size_t)BB * NCH * EE * EE]; // exclusive-prefix states
static __device__ __nv_bfloat16 S_lo[(size_t)BB * NCH * EE * EE];
static __device__ __nv_bfloat16 A_hi[(size_t)BB * NCH * CC * CC]; // masked QK^T
static __device__ __nv_bfloat16 A_lo[(size_t)BB * NCH * CC * CC];
static __device__ __nv_bfloat16 at_hi[(size_t)BB * TT * EE];      // attn output (split)
static __device__ __nv_bfloat16 at_lo[(size_t)BB * TT * EE];

static __device__ float g_z[(size_t)BB * NCH * EE];   // key colsums -> exclusive prefix
static __device__ float g_rs[(size_t)BB * NCH * CC];  // rowsum of masked A
static __device__ float g_dz[(size_t)BB * NCH * CC];  // q . z_excl

// ---------------------------------------------------------------------------
// helpers
// ---------------------------------------------------------------------------
__device__ __forceinline__ uint32_t smem_u32(const void* p) {
    uint32_t a;
    asm("{ .reg .u64 t; cvta.to.shared.u64 t, %1; cvt.u32.u64 %0, t; }" : "=r"(a) : "l"(p));
    return a;
}

__device__ __forceinline__ void ldm4(uint32_t* r, uint32_t addr) {
    asm volatile("ldmatrix.sync.aligned.m8n8.x4.shared.b16 {%0,%1,%2,%3}, [%4];"
                 : "=r"(r[0]), "=r"(r[1]), "=r"(r[2]), "=r"(r[3]) : "r"(addr));
}

__device__ __forceinline__ void mma16816(float* c, const uint32_t* a, uint32_t b0, uint32_t b1) {
    asm volatile(
        "mma.sync.aligned.m16n8k16.row.col.f32.bf16.bf16.f32 "
        "{%0,%1,%2,%3}, {%4,%5,%6,%7}, {%8,%9}, {%0,%1,%2,%3};"
        : "+f"(c[0]), "+f"(c[1]), "+f"(c[2]), "+f"(c[3])
        : "r"(a[0]), "r"(a[1]), "r"(a[2]), "r"(a[3]), "r"(b0), "r"(b1));
}

__device__ __forceinline__ void cpa16(uint32_t dst, const void* src) {
    asm volatile("cp.async.cg.shared.global [%0], [%1], 16;" :: "r"(dst), "l"(src));
}

__device__ __forceinline__ void split_pair(float x, float y, uint32_t& hi, uint32_t& lo) {
    __nv_bfloat16 hx = __float2bfloat16(x), hy = __float2bfloat16(y);
    __nv_bfloat16 lx = __float2bfloat16(x - __bfloat162float(hx));
    __nv_bfloat16 ly = __float2bfloat16(y - __bfloat162float(hy));
    hi = (uint32_t)__bfloat16_as_ushort(hx) | ((uint32_t)__bfloat16_as_ushort(hy) << 16);
    lo = (uint32_t)__bfloat16_as_ushort(lx) | ((uint32_t)__bfloat16_as_ushort(ly) << 16);
}

// ---------------------------------------------------------------------------
// block GEMM (128x128): C[m,n] += sum_k (Ahi+Alo)[m,k]*(Bhi+Blo)[n,k]
// BK=32, 3-stage cp.async pipeline, 128 threads, 4 warps (2m x 2n), warp 64x64
// ---------------------------------------------------------------------------
#define NSTAGE 3
#define STAGE_BYTES 32768
#define SMEM_BYTES (NSTAGE * STAGE_BYTES)

__device__ __forceinline__ void stage_load(
    uint32_t su, int buf,
    const __nv_bfloat16* __restrict__ ah, const __nv_bfloat16* __restrict__ al,
    const __nv_bfloat16* __restrict__ bh, const __nv_bfloat16* __restrict__ bl,
    int lda, int ldb, int kofs)
{
    uint32_t sb = su + (uint32_t)buf * STAGE_BYTES;
    int tid = threadIdx.x;
#pragma unroll
    for (int u = 0; u < 4; u++) {
        int ch = tid + u * 128;          // 0..511
        int row = ch >> 2, c16 = ch & 3; // 128 rows x 4 16B-chunks
        uint32_t so = (uint32_t)(row * 64 + ((c16 ^ ((row >> 1) & 3)) * 16));
        size_t goa = (size_t)row * lda + kofs + c16 * 8;
        size_t gob = (size_t)row * ldb + kofs + c16 * 8;
        cpa16(sb + so, ah + goa);
        cpa16(sb + 8192 + so, al + goa);
        cpa16(sb + 16384 + so, bh + gob);
        cpa16(sb + 24576 + so, bl + gob);
    }
    asm volatile("cp.async.commit_group;" ::: "memory");
}

__device__ __forceinline__ void gemm_prologue(
    uint32_t su,
    const __nv_bfloat16* __restrict__ ah, const __nv_bfloat16* __restrict__ al,
    const __nv_bfloat16* __restrict__ bh, const __nv_bfloat16* __restrict__ bl,
    int lda, int ldb, int nk)
{
#pragma unroll
    for (int s = 0; s < NSTAGE - 1; s++) {
        if (s < nk) stage_load(su, s, ah, al, bh, bl, lda, ldb, s * 32);
        else asm volatile("cp.async.commit_group;" ::: "memory");
    }
}

__device__ __forceinline__ void gemm_body(
    float (&acc)[4][8][4], uint32_t su,
    const __nv_bfloat16* __restrict__ ah, const __nv_bfloat16* __restrict__ al,
    const __nv_bfloat16* __restrict__ bh, const __nv_bfloat16* __restrict__ bl,
    int lda, int ldb, int nk)
{
    const int tid = threadIdx.x;
    const int lane = tid & 31, wid = tid >> 5;
    const int warp_m = wid >> 1, warp_n = wid & 1;
    const int q = lane >> 3, r8 = lane & 7;
    const int a_rowoff = warp_m * 64 + (q & 1) * 8 + r8;
    const int a_kcadd  = q >> 1;
    const int b_nbase  = warp_n * 64 + (q >> 1) * 8 + r8;
    const int b_kcadd  = q & 1;
    const int xor3a = (a_rowoff >> 1) & 3;
    const int xor3b = (b_nbase >> 1) & 3;

    for (int kc = 0; kc < nk; kc++) {
        asm volatile("cp.async.wait_group %0;" :: "n"(NSTAGE - 2) : "memory");
        __syncthreads();
        int pf = kc + NSTAGE - 1;
        if (pf < nk) stage_load(su, pf % NSTAGE, ah, al, bh, bl, lda, ldb, pf * 32);
        else asm volatile("cp.async.commit_group;" ::: "memory");

        uint32_t sb = su + (uint32_t)(kc % NSTAGE) * STAGE_BYTES;
        uint32_t a_base = sb + (uint32_t)(a_rowoff * 64);
        uint32_t b_base = sb + 16384u + (uint32_t)(b_nbase * 64);
#pragma unroll
        for (int ks = 0; ks < 2; ks++) {
            uint32_t Ah[4][4], Al[4][4];
            uint32_t a_ch = (uint32_t)((((ks * 2 + a_kcadd) ^ xor3a) & 3) * 16);
#pragma unroll
            for (int mt = 0; mt < 4; mt++) {
                uint32_t addr = a_base + (uint32_t)(mt * 1024) + a_ch;
                ldm4(Ah[mt], addr);
                ldm4(Al[mt], addr + 8192u);
            }
            uint32_t b_ch = (uint32_t)((((ks * 2 + b_kcadd) ^ xor3b) & 3) * 16);
#pragma unroll
            for (int nt = 0; nt < 4; nt++) {
                uint32_t Bh[4], Bl[4];
                uint32_t baddr = b_base + (uint32_t)(nt * 1024) + b_ch;
                ldm4(Bh, baddr);
                ldm4(Bl, baddr + 8192u);
#pragma unroll
                for (int mt = 0; mt < 4; mt++) {
#pragma unroll
                    for (int h = 0; h < 2; h++) {
                        float* c = acc[mt][nt * 2 + h];
                        mma16816(c, Ah[mt], Bh[2 * h], Bh[2 * h + 1]);
                        mma16816(c, Ah[mt], Bl[2 * h], Bl[2 * h + 1]);
                        mma16816(c, Al[mt], Bh[2 * h], Bh[2 * h + 1]);
                    }
                }
            }
        }
    }
}

__device__ __forceinline__ void gemm_block(
    float (&acc)[4][8][4], uint32_t su,
    const __nv_bfloat16* __restrict__ ah, const __nv_bfloat16* __restrict__ al,
    const __nv_bfloat16* __restrict__ bh, const __nv_bfloat16* __restrict__ bl,
    int lda, int ldb, int nk)
{
    __syncthreads();
    gemm_prologue(su, ah, al, bh, bl, lda, ldb, nk);
    gemm_body(acc, su, ah, al, bh, bl, lda, ldb, nk);
    __syncthreads();
}

#define ZERO_ACC(acc) do { \
    _Pragma("unroll") for (int _i = 0; _i < 4; _i++) \
    _Pragma("unroll") for (int _j = 0; _j < 8; _j++) \
    _Pragma("unroll") for (int _l = 0; _l < 4; _l++) acc[_i][_j][_l] = 0.f; \
} while (0)

// rows = warp_m*64 + mt*16 + h*8 + g; cols = warp_n*64 + nt*8 + tg*2
#define EPI_VARS \
    const int tid = threadIdx.x; \
    const int lane = tid & 31, wid = tid >> 5; \
    const int warp_m = wid >> 1, warp_n = wid & 1; \
    const int g = lane >> 2, tg = lane & 3;

#define TPAD 136   // padded row length (elems) for transpose buffer (16B-mult)

// ---------------------------------------------------------------------------
// q/k/v projections: D[t,j] = sum_e xT[t,e] * W[j,e] + bias
// which = which_base + blockIdx.z:
//   0 (q): fp32 row-major -> g_q
//   1 (k): exp -> split row-major, transpose -> kT, colsum -> g_z
//   2 (v): *toep[t] -> transpose -> vT
// ---------------------------------------------------------------------------
__global__ __launch_bounds__(128, 2) void gemm_proj_kernel(
    const float* __restrict__ qb, const float* __restrict__ kb,
    const float* __restrict__ vb, const float* __restrict__ toep, int which_base)
{
    extern __shared__ char sm[];
    __shared__ float zred[2][128];
    uint32_t su = smem_u32(sm);
    int m0 = blockIdx.x * 128, n0 = blockIdx.y * 128;
    int which = which_base + blockIdx.z;

    float acc[4][8][4];
    ZERO_ACC(acc);
    gemm_block(acc, su,
               xT_hi + (size_t)m0 * EE, xT_lo + (size_t)m0 * EE,
               w_hi + (size_t)which * EE * EE + (size_t)n0 * EE,
               w_lo + (size_t)which * EE * EE + (size_t)n0 * EE,
               EE, EE, 16);

    EPI_VARS;
    const int b = m0 / TT, t0g = m0 % TT;
    __nv_bfloat16* buf = (__nv_bfloat16*)sm;   // reuse gemm smem for transpose

    if (which == 0) {
#pragma unroll
        for (int mt = 0; mt < 4; mt++)
#pragma unroll
            for (int h = 0; h < 2; h++) {
                int row = m0 + warp_m * 64 + mt * 16 + h * 8 + g;
#pragma unroll
                for (int nt = 0; nt < 8; nt++) {
                    int col = n0 + warp_n * 64 + nt * 8 + tg * 2;
                    float2 o;
                    o.x = acc[mt][nt][2 * h] + qb[col];
                    o.y = acc[mt][nt][2 * h + 1] + qb[col + 1];
                    *(float2*)&g_q[(size_t)row * EE + col] = o;
                }
            }
        return;
    }

    if (which == 1) {
        float cs[16];
#pragma unroll
        for (int i = 0; i < 16; i++) cs[i] = 0.f;
#pragma unroll
        for (int mt = 0; mt < 4; mt++)
#pragma unroll
            for (int h = 0; h < 2; h++) {
                int row = warp_m * 64 + mt * 16 + h * 8 + g;
#pragma unroll
                for (int nt = 0; nt < 8; nt++) {
                    int col = warp_n * 64 + nt * 8 + tg * 2;
                    float v0 = expf(acc[mt][nt][2 * h]     + kb[n0 + col]);
                    float v1 = expf(acc[mt][nt][2 * h + 1] + kb[n0 + col + 1]);
                    acc[mt][nt][2 * h] = v0;
                    acc[mt][nt][2 * h + 1] = v1;
                    cs[nt * 2] += v0;
                    cs[nt * 2 + 1] += v1;
                    uint32_t hi, lo;
                    split_pair(v0, v1, hi, lo);
                    *(uint32_t*)&k_hi[(size_t)(m0 + row) * EE + n0 + col] = hi;
                    *(uint32_t*)&k_lo[(size_t)(m0 + row) * EE + n0 + col] = lo;
                }
            }
#pragma unroll
        for (int i = 0; i < 16; i++) {
            cs[i] += __shfl_xor_sync(0xffffffffu, cs[i], 4);
            cs[i] += __shfl_xor_sync(0xffffffffu, cs[i], 8);
            cs[i] += __shfl_xor_sync(0xffffffffu, cs[i], 16);
        }
        if (g == 0) {
#pragma unroll
            for (int nt = 0; nt < 8; nt++) {
                int col = warp_n * 64 + nt * 8 + tg * 2;
                zred[warp_m][col] = cs[nt * 2];
                zred[warp_m][col + 1] = cs[nt * 2 + 1];
            }
        }
    } else {
#pragma unroll
        for (int mt = 0; mt < 4; mt++)
#pragma unroll
            for (int h = 0; h < 2; h++) {
                int row = warp_m * 64 + mt * 16 + h * 8 + g;
                float tw = toep[t0g + row];
#pragma unroll
                for (int nt = 0; nt < 8; nt++) {
                    int col = warp_n * 64 + nt * 8 + tg * 2;
                    acc[mt][nt][2 * h]     = (acc[mt][nt][2 * h]     + vb[n0 + col]) * tw;
                    acc[mt][nt][2 * h + 1] = (acc[mt][nt][2 * h + 1] + vb[n0 + col + 1]) * tw;
                }
            }
    }

    __nv_bfloat16* dsth = (which == 1) ? kT_hi : vT_hi;
    __nv_bfloat16* dstl = (which == 1) ? kT_lo : vT_lo;

    // pass 1: hi transpose
#pragma unroll
    for (int mt = 0; mt < 4; mt++)
#pragma unroll
        for (int h = 0; h < 2; h++) {
            int row = warp_m * 64 + mt * 16 + h * 8 + g;
#pragma unroll
            for (int nt = 0; nt < 8; nt++) {
                int col = warp_n * 64 + nt * 8 + tg * 2;
                buf[(size_t)col * TPAD + row] = __float2bfloat16(acc[mt][nt][2 * h]);
                buf[(size_t)(col + 1) * TPAD + row] = __float2bfloat16(acc[mt][nt][2 * h + 1]);
            }
        }
    __syncthreads();
    if (which == 1) {
        int bc = b * NCH + t0g / CC;
        g_z[(size_t)bc * EE + n0 + tid] = zred[0][tid] + zred[1][tid];
    }
    {
        const uint4* src = (const uint4*)(buf + (size_t)tid * TPAD);
        uint4* dst = (uint4*)(dsth + ((size_t)b * EE + n0 + tid) * TT + t0g);
#pragma unroll
        for (int i = 0; i < 16; i++) dst[i] = src[i];
    }
    __syncthreads();
    // pass 2: lo transpose
#pragma unroll
    for (int mt = 0; mt < 4; mt++)
#pragma unroll
        for (int h = 0; h < 2; h++) {
            int row = warp_m * 64 + mt * 16 + h * 8 + g;
#pragma unroll
            for (int nt = 0; nt < 8; nt++) {
                int col = warp_n * 64 + nt * 8 + tg * 2;
                float v0 = acc[mt][nt][2 * h], v1 = acc[mt][nt][2 * h + 1];
                buf[(size_t)col * TPAD + row] =
                    __float2bfloat16(v0 - __bfloat162float(__float2bfloat16(v0)));
                buf[(size_t)(col + 1) * TPAD + row] =
                    __float2bfloat16(v1 - __bfloat162float(__float2bfloat16(v1)));
            }
        }
    __syncthreads();
    {
        const uint4* src = (const uint4*)(buf + (size_t)tid * TPAD);
        uint4* dst = (uint4*)(dstl + ((size_t)b * EE + n0 + tid) * TT + t0g);
#pragma unroll
        for (int i = 0; i < 16; i++) dst[i] = src[i];
    }
}

// ---------------------------------------------------------------------------
// fused chunk-state scan (128x128 tiles): per (m0, n0, b), chunks c = 0..15;
// prefetch chunk-c stages BEFORE storing S_c (hides the store); skip the
// last chunk's GEMM and the S_0 store (S_0 == 0; out kernel skips c==0 Q@S).
// ---------------------------------------------------------------------------
__global__ __launch_bounds__(128, 2) void gemm_hscan_kernel()
{
    extern __shared__ char sm[];
    uint32_t su = smem_u32(sm);
    int m0 = blockIdx.x * 128, n0 = blockIdx.y * 128;
    int b = blockIdx.z;

    float acc[4][8][4];
    ZERO_ACC(acc);
    EPI_VARS;
    (void)tid; (void)lane;

    for (int c = 0; c < NCH; c++) {
        int bc = b * NCH + c;
        const __nv_bfloat16* ah = vT_hi + ((size_t)b * EE + m0) * TT + (size_t)c * CC;
        const __nv_bfloat16* al = vT_lo + ((size_t)b * EE + m0) * TT + (size_t)c * CC;
        const __nv_bfloat16* bh = kT_hi + ((size_t)b * EE + n0) * TT + (size_t)c * CC;
        const __nv_bfloat16* bl = kT_lo + ((size_t)b * EE + n0) * TT + (size_t)c * CC;
        bool do_gemm = (c < NCH - 1);

        __syncthreads();
        if (do_gemm) gemm_prologue(su, ah, al, bh, bl, TT, TT, 4);

        if (c > 0) {
            __nv_bfloat16* Sh = S_hi + (size_t)bc * EE * EE;
            __nv_bfloat16* Sl = S_lo + (size_t)bc * EE * EE;
#pragma unroll
            for (int mt = 0; mt < 4; mt++)
#pragma unroll
                for (int h = 0; h < 2; h++) {
                    int row = m0 + warp_m * 64 + mt * 16 + h * 8 + g;
#pragma unroll
                    for (int nt = 0; nt < 8; nt++) {
                        int col = n0 + warp_n * 64 + nt * 8 + tg * 2;
                        uint32_t hi, lo;
                        split_pair(acc[mt][nt][2 * h], acc[mt][nt][2 * h + 1], hi, lo);
                        *(uint32_t*)&Sh[(size_t)row * EE + col] = hi;
                        *(uint32_t*)&Sl[(size_t)row * EE + col] = lo;
                    }
                }
        }
        if (do_gemm) gemm_body(acc, su, ah, al, bh, bl, TT, TT, 4);
    }
}

// ---------------------------------------------------------------------------
// A = causal-mask(Q K^T): rowsum -> g_rs, split bf16 -> A_hi/A_lo
// ---------------------------------------------------------------------------
__global__ __launch_bounds__(128, 2) void gemm_qk_kernel()
{
    extern __shared__ char sm[];
    __shared__ float s_rs[128][2];
    uint32_t su = smem_u32(sm);
    int bc = blockIdx.x, b = bc / NCH, c = bc % NCH;
    size_t base = ((size_t)b * TT + (size_t)c * CC) * EE;

    float acc[4][8][4];
    ZERO_ACC(acc);
    gemm_block(acc, su, q_hi + base, q_lo + base, k_hi + base, k_lo + base, EE, EE, 16);

    EPI_VARS;
    (void)lane;
    __nv_bfloat16* Ah = A_hi + (size_t)bc * CC * CC;
    __nv_bfloat16* Al = A_lo + (size_t)bc * CC * CC;
#pragma unroll
    for (int mt = 0; mt < 4; mt++)
#pragma unroll
        for (int h = 0; h < 2; h++) {
            int row = warp_m * 64 + mt * 16 + h * 8 + g;
            float rs = 0.f;
#pragma unroll
            for (int nt = 0; nt < 8; nt++) {
                int col = warp_n * 64 + nt * 8 + tg * 2;
                float v0 = acc[mt][nt][2 * h], v1 = acc[mt][nt][2 * h + 1];
                if (col > row) v0 = 0.f;
                if (col + 1 > row) v1 = 0.f;
                rs += v0 + v1;
                uint32_t hi, lo;
                split_pair(v0, v1, hi, lo);
                *(uint32_t*)&Ah[(size_t)row * CC + col] = hi;
                *(uint32_t*)&Al[(size_t)row * CC + col] = lo;
            }
            rs += __shfl_xor_sync(0xffffffffu, rs, 1);
            rs += __shfl_xor_sync(0xffffffffu, rs, 2);
            if (tg == 0) s_rs[row][warp_n] = rs;
        }
    __syncthreads();
    g_rs[(size_t)bc * CC + tid] = s_rs[tid][0] + s_rs[tid][1];
}

// ---------------------------------------------------------------------------
// out = (A @ V_c + Q @ S_c) / d, split -> at_hi/at_lo (Q@S skipped for c==0)
// ---------------------------------------------------------------------------
__global__ __launch_bounds__(128, 2) void gemm_out_kernel()
{
    extern __shared__ char sm[];
    uint32_t su = smem_u32(sm);
    int n0 = blockIdx.x * 128;
    int bc = blockIdx.y, b = bc / NCH, c = bc % NCH;

    float acc[4][8][4];
    ZERO_ACC(acc);
    gemm_block(acc, su,
               A_hi + (size_t)bc * CC * CC, A_lo + (size_t)bc * CC * CC,
               vT_hi + ((size_t)b * EE + n0) * TT + (size_t)c * CC,
               vT_lo + ((size_t)b * EE + n0) * TT + (size_t)c * CC,
               CC, TT, 4);
    if (c != 0) {
        size_t qbase = ((size_t)b * TT + (size_t)c * CC) * EE;
        gemm_block(acc, su,
                   q_hi + qbase, q_lo + qbase,
                   S_hi + (size_t)bc * EE * EE + (size_t)n0 * EE,
                   S_lo + (size_t)bc * EE * EE + (size_t)n0 * EE,
                   EE, EE, 16);
    }

    EPI_VARS;
    (void)tid; (void)lane;
#pragma unroll
    for (int mt = 0; mt < 4; mt++)
#pragma unroll
        for (int h = 0; h < 2; h++) {
            int row = warp_m * 64 + mt * 16 + h * 8 + g;
            float d = fmaxf(g_rs[(size_t)bc * CC + row] + g_dz[(size_t)bc * CC + row], EPSV);
            float inv = 1.0f / d;
            size_t ob = ((size_t)b * TT + (size_t)c * CC + row) * EE + n0;
#pragma unroll
            for (int nt = 0; nt < 8; nt++) {
                int col = warp_n * 64 + nt * 8 + tg * 2;
                uint32_t hi, lo;
                split_pair(acc[mt][nt][2 * h] * inv, acc[mt][nt][2 * h + 1] * inv, hi, lo);
                *(uint32_t*)&at_hi[ob + col] = hi;
                *(uint32_t*)&at_lo[ob + col] = lo;
            }
        }
}

// ---------------------------------------------------------------------------
// output projection -> d_out
// ---------------------------------------------------------------------------
__global__ __launch_bounds__(128, 2) void gemm_oproj_kernel(
    const float* __restrict__ ob_bias, float* __restrict__ outp)
{
    extern __shared__ char sm[];
    uint32_t su = smem_u32(sm);
    int m0 = blockIdx.x * 128, n0 = blockIdx.y * 128;

    float acc[4][8][4];
    ZERO_ACC(acc);
    gemm_block(acc, su,
               at_hi + (size_t)m0 * EE, at_lo + (size_t)m0 * EE,
               w_hi + (size_t)3 * EE * EE + (size_t)n0 * EE,
               w_lo + (size_t)3 * EE * EE + (size_t)n0 * EE,
               EE, EE, 16);

    EPI_VARS;
    (void)tid; (void)lane;
#pragma unroll
    for (int mt = 0; mt < 4; mt++)
#pragma unroll
        for (int h = 0; h < 2; h++) {
            int row = m0 + warp_m * 64 + mt * 16 + h * 8 + g;
#pragma unroll
            for (int nt = 0; nt < 8; nt++) {
                int col = n0 + warp_n * 64 + nt * 8 + tg * 2;
                float2 o;
                o.x = acc[mt][nt][2 * h] + ob_bias[col];
                o.y = acc[mt][nt][2 * h + 1] + ob_bias[col + 1];
                *(float2*)&outp[(size_t)row * EE + col] = o;
            }
        }
}

// ---------------------------------------------------------------------------
// conversion / elementwise kernels
// ---------------------------------------------------------------------------
__global__ __launch_bounds__(256) void conv_w_kernel(
    const float* __restrict__ qw, const float* __restrict__ kw,
    const float* __restrict__ vw, const float* __restrict__ ow)
{
    size_t idx = (size_t)blockIdx.x * 256 + threadIdx.x;
    if (idx >= (size_t)4 * EE * EE) return;
    int which = (int)(idx / ((size_t)EE * EE));
    size_t rem = idx % ((size_t)EE * EE);
    const float* w = (which == 0) ? qw : (which == 1) ? kw : (which == 2) ? vw : ow;
    float x = w[rem];
    __nv_bfloat16 h = __float2bfloat16(x);
    w_hi[idx] = h;
    w_lo[idx] = __float2bfloat16(x - __bfloat162float(h));
}

// x (B,E,T) fp32 -> xT (B,T,E) bf16 split
__global__ __launch_bounds__(256) void conv_xT_kernel(const float* __restrict__ x)
{
    __shared__ float ts[32][33];
    int b = blockIdx.z;
    int t0 = blockIdx.x * 32, e0 = blockIdx.y * 32;
    int tx = threadIdx.x, ty = threadIdx.y;  // (32,8)
    const float* xb = x + (size_t)b * EE * TT;
#pragma unroll
    for (int i = 0; i < 4; i++)
        ts[ty + i * 8][tx] = xb[(size_t)(e0 + ty + i * 8) * TT + t0 + tx];
    __syncthreads();
    size_t ob = (size_t)b * TT * EE;
#pragma unroll
    for (int i = 0; i < 4; i++) {
        float val = ts[tx][ty + i * 8];
        __nv_bfloat16 h = __float2bfloat16(val);
        size_t o = ob + (size_t)(t0 + ty + i * 8) * EE + e0 + tx;
        xT_hi[o] = h;
        xT_lo[o] = __float2bfloat16(val - __bfloat162float(h));
    }
}

// q softmax + split
__global__ __launch_bounds__(128) void act_kernel()
{
    int bt = blockIdx.x;
    int tid = threadIdx.x;
    size_t base = (size_t)bt * EE;
    __shared__ float sred[4];

    float qv[4];
#pragma unroll
    for (int u = 0; u < 4; u++) qv[u] = g_q[base + tid + u * 128];
    float m = fmaxf(fmaxf(qv[0], qv[1]), fmaxf(qv[2], qv[3]));
#pragma unroll
    for (int o = 16; o; o >>= 1) m = fmaxf(m, __shfl_xor_sync(0xffffffffu, m, o));
    if ((tid & 31) == 0) sred[tid >> 5] = m;
    __syncthreads();
    m = fmaxf(fmaxf(sred[0], sred[1]), fmaxf(sred[2], sred[3]));
    __syncthreads();
    float s = 0.f;
#pragma unroll
    for (int u = 0; u < 4; u++) { qv[u] = expf(qv[u] - m); s += qv[u]; }
#pragma unroll
    for (int o = 16; o; o >>= 1) s += __shfl_xor_sync(0xffffffffu, s, o);
    if ((tid & 31) == 0) sred[tid >> 5] = s;
    __syncthreads();
    s = sred[0] + sred[1] + sred[2] + sred[3];
    float scale = INV_SQRT_E / s;
#pragma unroll
    for (int u = 0; u < 4; u++) {
        size_t idx = base + tid + u * 128;
        float val = qv[u] * scale;
        __nv_bfloat16 h = __float2bfloat16(val);
        q_hi[idx] = h;
        q_lo[idx] = __float2bfloat16(val - __bfloat162float(h));
    }
}

__global__ __launch_bounds__(128) void zprefix_kernel()
{
    int idx = blockIdx.x * blockDim.x + threadIdx.x;
    if (idx >= BB * EE) return;
    int b = idx / EE, off = idx % EE;
    float run = 0.f;
    float* p = g_z + (size_t)b * NCH * EE + off;
#pragma unroll
    for (int c = 0; c < NCH; c++) {
        float tmp = *p; *p = run; run += tmp; p += EE;
    }
}

// dz[b,c,i] = sum_e q[b, c*128+i, e] * z_excl[b,c,e]   (q from split)
__global__ __launch_bounds__(256) void dz_kernel()
{
    int bc = blockIdx.x;
    int b = bc / NCH, c = bc % NCH;
    int w = threadIdx.x >> 5, lane = threadIdx.x & 31;
    const float* z = g_z + (size_t)bc * EE;
#pragma unroll
    for (int it = 0; it < 16; it++) {
        int i = it * 8 + w;
        size_t qrow = ((size_t)b * TT + (size_t)c * CC + i) * EE;
        float s = 0.f;
#pragma unroll 4
        for (int j = lane; j < EE; j += 32) {
            float qv = __bfloat162float(q_hi[qrow + j]) + __bfloat162float(q_lo[qrow + j]);
            s += qv * z[j];
        }
#pragma unroll
        for (int o = 16; o; o >>= 1) s += __shfl_xor_sync(0xffffffffu, s, o);
        if (lane == 0) g_dz[(size_t)bc * CC + i] = s;
    }
}

// ---------------------------------------------------------------------------
extern "C" void kernel_launch(void* const* d_in, const int* in_sizes, int n_in,
                              void* d_out, int out_size)
{
    const float* x    = (const float*)d_in[0];
    const float* toep = (const float*)d_in[1];
    const float* qw   = (const float*)d_in[2];
    const float* qb   = (const float*)d_in[3];
    const float* kw   = (const float*)d_in[4];
    const float* kb   = (const float*)d_in[5];
    const float* vw   = (const float*)d_in[6];
    const float* vb   = (const float*)d_in[7];
    const float* ow   = (const float*)d_in[8];
    const float* ob   = (const float*)d_in[9];
    float* out = (float*)d_out;

    static cudaStream_t s_aux = nullptr;
    static cudaEvent_t ev_fork = nullptr, ev_kv = nullptr, ev_join = nullptr;
    static int attr_done = 0;
    if (!attr_done) {
        cudaFuncSetAttribute(gemm_proj_kernel,  cudaFuncAttributeMaxDynamicSharedMemorySize, SMEM_BYTES);
        cudaFuncSetAttribute(gemm_hscan_kernel, cudaFuncAttributeMaxDynamicSharedMemorySize, SMEM_BYTES);
        cudaFuncSetAttribute(gemm_qk_kernel,    cudaFuncAttributeMaxDynamicSharedMemorySize, SMEM_BYTES);
        cudaFuncSetAttribute(gemm_out_kernel,   cudaFuncAttributeMaxDynamicSharedMemorySize, SMEM_BYTES);
        cudaFuncSetAttribute(gemm_oproj_kernel, cudaFuncAttributeMaxDynamicSharedMemorySize, SMEM_BYTES);
        cudaStreamCreateWithFlags(&s_aux, cudaStreamNonBlocking);
        cudaEventCreateWithFlags(&ev_fork, cudaEventDisableTiming);
        cudaEventCreateWithFlags(&ev_kv,   cudaEventDisableTiming);
        cudaEventCreateWithFlags(&ev_join, cudaEventDisableTiming);
        attr_done = 1;
    }

    // main: conversions
    conv_w_kernel<<<(int)(((size_t)4 * EE * EE + 255) / 256), 256>>>(qw, kw, vw, ow);
    conv_xT_kernel<<<dim3(TT / 32, EE / 32, BB), dim3(32, 8)>>>(x);

    // fork after conversions: aux does the q pipeline, main does k/v + hscan
    cudaEventRecord(ev_fork, 0);
    cudaStreamWaitEvent(s_aux, ev_fork, 0);

    // aux: q projection + softmax/split
    gemm_proj_kernel<<<dim3(BB * TT / 128, EE / 128, 1), 128, SMEM_BYTES, s_aux>>>(
        qb, kb, vb, toep, 0);
    act_kernel<<<BB * TT, 128, 0, s_aux>>>();

    // main: k/v projections, then state scan
    gemm_proj_kernel<<<dim3(BB * TT / 128, EE / 128, 2), 128, SMEM_BYTES>>>(
        qb, kb, vb, toep, 1);
    cudaEventRecord(ev_kv, 0);
    gemm_hscan_kernel<<<dim3(EE / 128, EE / 128, BB), 128, SMEM_BYTES>>>();

    // aux (needs k/v results): zprefix, qk, dz
    cudaStreamWaitEvent(s_aux, ev_kv, 0);
    zprefix_kernel<<<(BB * EE + 127) / 128, 128, 0, s_aux>>>();
    gemm_qk_kernel<<<BB * NCH, 128, SMEM_BYTES, s_aux>>>();
    dz_kernel<<<BB * NCH, 256, 0, s_aux>>>();
    cudaEventRecord(ev_join, s_aux);

    // main: join, then out + oproj
    cudaStreamWaitEvent(0, ev_join, 0);
    gemm_out_kernel<<<dim3(EE / 128, BB * NCH), 128, SMEM_BYTES>>>();
    gemm_oproj_kernel<<<dim3(BB * TT / 128, EE / 128), 128, SMEM_BYTES>>>(ob, out);
}

// round 16
// speedup vs baseline: 1.2911x; 1.2911x over previous
#include <cuda_runtime.h>
#include <cuda_bf16.h>
#include <math.h>
#include <stdint.h>

#define BB 8
#define TT 2048
#define EE 512
#define CC 128
#define NCH 16
#define EPSV 1e-3f
#define INV_SQRT_E 0.04419417382415922f  // 512^-0.5

// ---------------------------------------------------------------------------
// scratch (device globals; no cudaMalloc allowed)
// ---------------------------------------------------------------------------
static __device__ float g_q[(size_t)BB * TT * EE];   // fp32 q (pre-softmax)

static __device__ __nv_bfloat16 xT_hi[(size_t)BB * TT * EE];
static __device__ __nv_bfloat16 xT_lo[(size_t)BB * TT * EE];
static __device__ __nv_bfloat16 w_hi[(size_t)4 * EE * EE];  // q,k,v,o
static __device__ __nv_bfloat16 w_lo[(size_t)4 * EE * EE];
static __device__ __nv_bfloat16 q_hi[(size_t)BB * TT * EE];
static __device__ __nv_bfloat16 q_lo[(size_t)BB * TT * EE];
static __device__ __nv_bfloat16 k_hi[(size_t)BB * TT * EE];
static __device__ __nv_bfloat16 k_lo[(size_t)BB * TT * EE];
static __device__ __nv_bfloat16 kT_hi[(size_t)BB * EE * TT];
static __device__ __nv_bfloat16 kT_lo[(size_t)BB * EE * TT];
static __device__ __nv_bfloat16 vT_hi[(size_t)BB * EE * TT];
static __device__ __nv_bfloat16 vT_lo[(size_t)BB * EE * TT];
static __device__ __nv_bfloat16 S_hi[(size_t)BB * NCH * EE * EE]; // exclusive-prefix states
static __device__ __nv_bfloat16 S_lo[(size_t)BB * NCH * EE * EE];
static __device__ __nv_bfloat16 A_hi[(size_t)BB * NCH * CC * CC]; // masked QK^T
static __device__ __nv_bfloat16 A_lo[(size_t)BB * NCH * CC * CC];
static __device__ __nv_bfloat16 at_hi[(size_t)BB * TT * EE];      // attn output (split)
static __device__ __nv_bfloat16 at_lo[(size_t)BB * TT * EE];

static __device__ float g_z[(size_t)BB * NCH * EE];   // key colsums -> exclusive prefix
static __device__ float g_rs[(size_t)BB * NCH * CC];  // rowsum of masked A
static __device__ float g_dz[(size_t)BB * NCH * CC];  // q . z_excl

// ---------------------------------------------------------------------------
// helpers
// ---------------------------------------------------------------------------
__device__ __forceinline__ uint32_t smem_u32(const void* p) {
    uint32_t a;
    asm("{ .reg .u64 t; cvta.to.shared.u64 t, %1; cvt.u32.u64 %0, t; }" : "=r"(a) : "l"(p));
    return a;
}

__device__ __forceinline__ void ldm4(uint32_t* r, uint32_t addr) {
    asm volatile("ldmatrix.sync.aligned.m8n8.x4.shared.b16 {%0,%1,%2,%3}, [%4];"
                 : "=r"(r[0]), "=r"(r[1]), "=r"(r[2]), "=r"(r[3]) : "r"(addr));
}

__device__ __forceinline__ void mma16816(float* c, const uint32_t* a, uint32_t b0, uint32_t b1) {
    asm volatile(
        "mma.sync.aligned.m16n8k16.row.col.f32.bf16.bf16.f32 "
        "{%0,%1,%2,%3}, {%4,%5,%6,%7}, {%8,%9}, {%0,%1,%2,%3};"
        : "+f"(c[0]), "+f"(c[1]), "+f"(c[2]), "+f"(c[3])
        : "r"(a[0]), "r"(a[1]), "r"(a[2]), "r"(a[3]), "r"(b0), "r"(b1));
}

__device__ __forceinline__ void cpa16(uint32_t dst, const void* src) {
    asm volatile("cp.async.cg.shared.global [%0], [%1], 16;" :: "r"(dst), "l"(src));
}

__device__ __forceinline__ void split_pair(float x, float y, uint32_t& hi, uint32_t& lo) {
    __nv_bfloat16 hx = __float2bfloat16(x), hy = __float2bfloat16(y);
    __nv_bfloat16 lx = __float2bfloat16(x - __bfloat162float(hx));
    __nv_bfloat16 ly = __float2bfloat16(y - __bfloat162float(hy));
    hi = (uint32_t)__bfloat16_as_ushort(hx) | ((uint32_t)__bfloat16_as_ushort(hy) << 16);
    lo = (uint32_t)__bfloat16_as_ushort(lx) | ((uint32_t)__bfloat16_as_ushort(ly) << 16);
}

// ---------------------------------------------------------------------------
// block GEMM (128x128): C[m,n] += sum_k (Ahi+Alo)[m,k]*(Bhi+Blo)[n,k]
// BK=32, 3-stage cp.async pipeline, 128 threads, 4 warps (2m x 2n), warp 64x64
// ---------------------------------------------------------------------------
#define NSTAGE 3
#define STAGE_BYTES 32768
#define SMEM_BYTES (NSTAGE * STAGE_BYTES)

__device__ __forceinline__ void stage_load(
    uint32_t su, int buf,
    const __nv_bfloat16* __restrict__ ah, const __nv_bfloat16* __restrict__ al,
    const __nv_bfloat16* __restrict__ bh, const __nv_bfloat16* __restrict__ bl,
    int lda, int ldb, int kofs)
{
    uint32_t sb = su + (uint32_t)buf * STAGE_BYTES;
    int tid = threadIdx.x;
#pragma unroll
    for (int u = 0; u < 4; u++) {
        int ch = tid + u * 128;          // 0..511
        int row = ch >> 2, c16 = ch & 3; // 128 rows x 4 16B-chunks
        uint32_t so = (uint32_t)(row * 64 + ((c16 ^ ((row >> 1) & 3)) * 16));
        size_t goa = (size_t)row * lda + kofs + c16 * 8;
        size_t gob = (size_t)row * ldb + kofs + c16 * 8;
        cpa16(sb + so, ah + goa);
        cpa16(sb + 8192 + so, al + goa);
        cpa16(sb + 16384 + so, bh + gob);
        cpa16(sb + 24576 + so, bl + gob);
    }
    asm volatile("cp.async.commit_group;" ::: "memory");
}

__device__ __forceinline__ void gemm_prologue(
    uint32_t su,
    const __nv_bfloat16* __restrict__ ah, const __nv_bfloat16* __restrict__ al,
    const __nv_bfloat16* __restrict__ bh, const __nv_bfloat16* __restrict__ bl,
    int lda, int ldb, int nk)
{
#pragma unroll
    for (int s = 0; s < NSTAGE - 1; s++) {
        if (s < nk) stage_load(su, s, ah, al, bh, bl, lda, ldb, s * 32);
        else asm volatile("cp.async.commit_group;" ::: "memory");
    }
}

__device__ __forceinline__ void gemm_body(
    float (&acc)[4][8][4], uint32_t su,
    const __nv_bfloat16* __restrict__ ah, const __nv_bfloat16* __restrict__ al,
    const __nv_bfloat16* __restrict__ bh, const __nv_bfloat16* __restrict__ bl,
    int lda, int ldb, int nk)
{
    const int tid = threadIdx.x;
    const int lane = tid & 31, wid = tid >> 5;
    const int warp_m = wid >> 1, warp_n = wid & 1;
    const int q = lane >> 3, r8 = lane & 7;
    const int a_rowoff = warp_m * 64 + (q & 1) * 8 + r8;
    const int a_kcadd  = q >> 1;
    const int b_nbase  = warp_n * 64 + (q >> 1) * 8 + r8;
    const int b_kcadd  = q & 1;
    const int xor3a = (a_rowoff >> 1) & 3;
    const int xor3b = (b_nbase >> 1) & 3;

    for (int kc = 0; kc < nk; kc++) {
        asm volatile("cp.async.wait_group %0;" :: "n"(NSTAGE - 2) : "memory");
        __syncthreads();
        int pf = kc + NSTAGE - 1;
        if (pf < nk) stage_load(su, pf % NSTAGE, ah, al, bh, bl, lda, ldb, pf * 32);
        else asm volatile("cp.async.commit_group;" ::: "memory");

        uint32_t sb = su + (uint32_t)(kc % NSTAGE) * STAGE_BYTES;
        uint32_t a_base = sb + (uint32_t)(a_rowoff * 64);
        uint32_t b_base = sb + 16384u + (uint32_t)(b_nbase * 64);
#pragma unroll
        for (int ks = 0; ks < 2; ks++) {
            uint32_t Ah[4][4], Al[4][4];
            uint32_t a_ch = (uint32_t)((((ks * 2 + a_kcadd) ^ xor3a) & 3) * 16);
#pragma unroll
            for (int mt = 0; mt < 4; mt++) {
                uint32_t addr = a_base + (uint32_t)(mt * 1024) + a_ch;
                ldm4(Ah[mt], addr);
                ldm4(Al[mt], addr + 8192u);
            }
            uint32_t b_ch = (uint32_t)((((ks * 2 + b_kcadd) ^ xor3b) & 3) * 16);
#pragma unroll
            for (int nt = 0; nt < 4; nt++) {
                uint32_t Bh[4], Bl[4];
                uint32_t baddr = b_base + (uint32_t)(nt * 1024) + b_ch;
                ldm4(Bh, baddr);
                ldm4(Bl, baddr + 8192u);
#pragma unroll
                for (int mt = 0; mt < 4; mt++) {
#pragma unroll
                    for (int h = 0; h < 2; h++) {
                        float* c = acc[mt][nt * 2 + h];
                        mma16816(c, Ah[mt], Bh[2 * h], Bh[2 * h + 1]);
                        mma16816(c, Ah[mt], Bl[2 * h], Bl[2 * h + 1]);
                        mma16816(c, Al[mt], Bh[2 * h], Bh[2 * h + 1]);
                    }
                }
            }
        }
    }
}

__device__ __forceinline__ void gemm_block(
    float (&acc)[4][8][4], uint32_t su,
    const __nv_bfloat16* __restrict__ ah, const __nv_bfloat16* __restrict__ al,
    const __nv_bfloat16* __restrict__ bh, const __nv_bfloat16* __restrict__ bl,
    int lda, int ldb, int nk)
{
    __syncthreads();
    gemm_prologue(su, ah, al, bh, bl, lda, ldb, nk);
    gemm_body(acc, su, ah, al, bh, bl, lda, ldb, nk);
    __syncthreads();
}

#define ZERO_ACC(acc) do { \
    _Pragma("unroll") for (int _i = 0; _i < 4; _i++) \
    _Pragma("unroll") for (int _j = 0; _j < 8; _j++) \
    _Pragma("unroll") for (int _l = 0; _l < 4; _l++) acc[_i][_j][_l] = 0.f; \
} while (0)

// rows = warp_m*64 + mt*16 + h*8 + g; cols = warp_n*64 + nt*8 + tg*2
#define EPI_VARS \
    const int tid = threadIdx.x; \
    const int lane = tid & 31, wid = tid >> 5; \
    const int warp_m = wid >> 1, warp_n = wid & 1; \
    const int g = lane >> 2, tg = lane & 3;

#define TPAD 136   // padded row length (elems) for transpose buffer (16B-mult)

// ---------------------------------------------------------------------------
// q/k/v projections: D[t,j] = sum_e xT[t,e] * W[j,e] + bias
// which = which_base + blockIdx.z:
//   0 (q): fp32 row-major -> g_q
//   1 (k): exp -> split row-major, transpose -> kT, colsum -> g_z
//   2 (v): *toep[t] -> transpose -> vT
// ---------------------------------------------------------------------------
__global__ __launch_bounds__(128, 2) void gemm_proj_kernel(
    const float* __restrict__ qb, const float* __restrict__ kb,
    const float* __restrict__ vb, const float* __restrict__ toep, int which_base)
{
    extern __shared__ char sm[];
    __shared__ float zred[2][128];
    uint32_t su = smem_u32(sm);
    int m0 = blockIdx.x * 128, n0 = blockIdx.y * 128;
    int which = which_base + blockIdx.z;

    float acc[4][8][4];
    ZERO_ACC(acc);
    gemm_block(acc, su,
               xT_hi + (size_t)m0 * EE, xT_lo + (size_t)m0 * EE,
               w_hi + (size_t)which * EE * EE + (size_t)n0 * EE,
               w_lo + (size_t)which * EE * EE + (size_t)n0 * EE,
               EE, EE, 16);

    EPI_VARS;
    const int b = m0 / TT, t0g = m0 % TT;
    __nv_bfloat16* buf = (__nv_bfloat16*)sm;   // reuse gemm smem for transpose

    if (which == 0) {
#pragma unroll
        for (int mt = 0; mt < 4; mt++)
#pragma unroll
            for (int h = 0; h < 2; h++) {
                int row = m0 + warp_m * 64 + mt * 16 + h * 8 + g;
#pragma unroll
                for (int nt = 0; nt < 8; nt++) {
                    int col = n0 + warp_n * 64 + nt * 8 + tg * 2;
                    float2 o;
                    o.x = acc[mt][nt][2 * h] + qb[col];
                    o.y = acc[mt][nt][2 * h + 1] + qb[col + 1];
                    *(float2*)&g_q[(size_t)row * EE + col] = o;
                }
            }
        return;
    }

    if (which == 1) {
        float cs[16];
#pragma unroll
        for (int i = 0; i < 16; i++) cs[i] = 0.f;
#pragma unroll
        for (int mt = 0; mt < 4; mt++)
#pragma unroll
            for (int h = 0; h < 2; h++) {
                int row = warp_m * 64 + mt * 16 + h * 8 + g;
#pragma unroll
                for (int nt = 0; nt < 8; nt++) {
                    int col = warp_n * 64 + nt * 8 + tg * 2;
                    float v0 = expf(acc[mt][nt][2 * h]     + kb[n0 + col]);
                    float v1 = expf(acc[mt][nt][2 * h + 1] + kb[n0 + col + 1]);
                    acc[mt][nt][2 * h] = v0;
                    acc[mt][nt][2 * h + 1] = v1;
                    cs[nt * 2] += v0;
                    cs[nt * 2 + 1] += v1;
                    uint32_t hi, lo;
                    split_pair(v0, v1, hi, lo);
                    *(uint32_t*)&k_hi[(size_t)(m0 + row) * EE + n0 + col] = hi;
                    *(uint32_t*)&k_lo[(size_t)(m0 + row) * EE + n0 + col] = lo;
                }
            }
#pragma unroll
        for (int i = 0; i < 16; i++) {
            cs[i] += __shfl_xor_sync(0xffffffffu, cs[i], 4);
            cs[i] += __shfl_xor_sync(0xffffffffu, cs[i], 8);
            cs[i] += __shfl_xor_sync(0xffffffffu, cs[i], 16);
        }
        if (g == 0) {
#pragma unroll
            for (int nt = 0; nt < 8; nt++) {
                int col = warp_n * 64 + nt * 8 + tg * 2;
                zred[warp_m][col] = cs[nt * 2];
                zred[warp_m][col + 1] = cs[nt * 2 + 1];
            }
        }
    } else {
#pragma unroll
        for (int mt = 0; mt < 4; mt++)
#pragma unroll
            for (int h = 0; h < 2; h++) {
                int row = warp_m * 64 + mt * 16 + h * 8 + g;
                float tw = toep[t0g + row];
#pragma unroll
                for (int nt = 0; nt < 8; nt++) {
                    int col = warp_n * 64 + nt * 8 + tg * 2;
                    acc[mt][nt][2 * h]     = (acc[mt][nt][2 * h]     + vb[n0 + col]) * tw;
                    acc[mt][nt][2 * h + 1] = (acc[mt][nt][2 * h + 1] + vb[n0 + col + 1]) * tw;
                }
            }
    }

    __nv_bfloat16* dsth = (which == 1) ? kT_hi : vT_hi;
    __nv_bfloat16* dstl = (which == 1) ? kT_lo : vT_lo;

    // pass 1: hi transpose
#pragma unroll
    for (int mt = 0; mt < 4; mt++)
#pragma unroll
        for (int h = 0; h < 2; h++) {
            int row = warp_m * 64 + mt * 16 + h * 8 + g;
#pragma unroll
            for (int nt = 0; nt < 8; nt++) {
                int col = warp_n * 64 + nt * 8 + tg * 2;
                buf[(size_t)col * TPAD + row] = __float2bfloat16(acc[mt][nt][2 * h]);
                buf[(size_t)(col + 1) * TPAD + row] = __float2bfloat16(acc[mt][nt][2 * h + 1]);
            }
        }
    __syncthreads();
    if (which == 1) {
        int bc = b * NCH + t0g / CC;
        g_z[(size_t)bc * EE + n0 + tid] = zred[0][tid] + zred[1][tid];
    }
    {
        const uint4* src = (const uint4*)(buf + (size_t)tid * TPAD);
        uint4* dst = (uint4*)(dsth + ((size_t)b * EE + n0 + tid) * TT + t0g);
#pragma unroll
        for (int i = 0; i < 16; i++) dst[i] = src[i];
    }
    __syncthreads();
    // pass 2: lo transpose
#pragma unroll
    for (int mt = 0; mt < 4; mt++)
#pragma unroll
        for (int h = 0; h < 2; h++) {
            int row = warp_m * 64 + mt * 16 + h * 8 + g;
#pragma unroll
            for (int nt = 0; nt < 8; nt++) {
                int col = warp_n * 64 + nt * 8 + tg * 2;
                float v0 = acc[mt][nt][2 * h], v1 = acc[mt][nt][2 * h + 1];
                buf[(size_t)col * TPAD + row] =
                    __float2bfloat16(v0 - __bfloat162float(__float2bfloat16(v0)));
                buf[(size_t)(col + 1) * TPAD + row] =
                    __float2bfloat16(v1 - __bfloat162float(__float2bfloat16(v1)));
            }
        }
    __syncthreads();
    {
        const uint4* src = (const uint4*)(buf + (size_t)tid * TPAD);
        uint4* dst = (uint4*)(dstl + ((size_t)b * EE + n0 + tid) * TT + t0g);
#pragma unroll
        for (int i = 0; i < 16; i++) dst[i] = src[i];
    }
}

// ---------------------------------------------------------------------------
// fused chunk-state scan (128x128 tiles): per (m0, n0, b), chunks c = 0..15;
// prefetch chunk-c stages BEFORE storing S_c (hides the store); skip the
// last chunk's GEMM and the S_0 store (S_0 == 0; out kernel skips c==0 Q@S).
// ---------------------------------------------------------------------------
__global__ __launch_bounds__(128, 2) void gemm_hscan_kernel()
{
    extern __shared__ char sm[];
    uint32_t su = smem_u32(sm);
    int m0 = blockIdx.x * 128, n0 = blockIdx.y * 128;
    int b = blockIdx.z;

    float acc[4][8][4];
    ZERO_ACC(acc);
    EPI_VARS;
    (void)tid; (void)lane;

    for (int c = 0; c < NCH; c++) {
        int bc = b * NCH + c;
        const __nv_bfloat16* ah = vT_hi + ((size_t)b * EE + m0) * TT + (size_t)c * CC;
        const __nv_bfloat16* al = vT_lo + ((size_t)b * EE + m0) * TT + (size_t)c * CC;
        const __nv_bfloat16* bh = kT_hi + ((size_t)b * EE + n0) * TT + (size_t)c * CC;
        const __nv_bfloat16* bl = kT_lo + ((size_t)b * EE + n0) * TT + (size_t)c * CC;
        bool do_gemm = (c < NCH - 1);

        __syncthreads();
        if (do_gemm) gemm_prologue(su, ah, al, bh, bl, TT, TT, 4);

        if (c > 0) {
            __nv_bfloat16* Sh = S_hi + (size_t)bc * EE * EE;
            __nv_bfloat16* Sl = S_lo + (size_t)bc * EE * EE;
#pragma unroll
            for (int mt = 0; mt < 4; mt++)
#pragma unroll
                for (int h = 0; h < 2; h++) {
                    int row = m0 + warp_m * 64 + mt * 16 + h * 8 + g;
#pragma unroll
                    for (int nt = 0; nt < 8; nt++) {
                        int col = n0 + warp_n * 64 + nt * 8 + tg * 2;
                        uint32_t hi, lo;
                        split_pair(acc[mt][nt][2 * h], acc[mt][nt][2 * h + 1], hi, lo);
                        *(uint32_t*)&Sh[(size_t)row * EE + col] = hi;
                        *(uint32_t*)&Sl[(size_t)row * EE + col] = lo;
                    }
                }
        }
        if (do_gemm) gemm_body(acc, su, ah, al, bh, bl, TT, TT, 4);
    }
}

// ---------------------------------------------------------------------------
// A = causal-mask(Q K^T): rowsum -> g_rs, split bf16 -> A_hi/A_lo
// ---------------------------------------------------------------------------
__global__ __launch_bounds__(128, 2) void gemm_qk_kernel()
{
    extern __shared__ char sm[];
    __shared__ float s_rs[128][2];
    uint32_t su = smem_u32(sm);
    int bc = blockIdx.x, b = bc / NCH, c = bc % NCH;
    size_t base = ((size_t)b * TT + (size_t)c * CC) * EE;

    float acc[4][8][4];
    ZERO_ACC(acc);
    gemm_block(acc, su, q_hi + base, q_lo + base, k_hi + base, k_lo + base, EE, EE, 16);

    EPI_VARS;
    (void)lane;
    __nv_bfloat16* Ah = A_hi + (size_t)bc * CC * CC;
    __nv_bfloat16* Al = A_lo + (size_t)bc * CC * CC;
#pragma unroll
    for (int mt = 0; mt < 4; mt++)
#pragma unroll
        for (int h = 0; h < 2; h++) {
            int row = warp_m * 64 + mt * 16 + h * 8 + g;
            float rs = 0.f;
#pragma unroll
            for (int nt = 0; nt < 8; nt++) {
                int col = warp_n * 64 + nt * 8 + tg * 2;
                float v0 = acc[mt][nt][2 * h], v1 = acc[mt][nt][2 * h + 1];
                if (col > row) v0 = 0.f;
                if (col + 1 > row) v1 = 0.f;
                rs += v0 + v1;
                uint32_t hi, lo;
                split_pair(v0, v1, hi, lo);
                *(uint32_t*)&Ah[(size_t)row * CC + col] = hi;
                *(uint32_t*)&Al[(size_t)row * CC + col] = lo;
            }
            rs += __shfl_xor_sync(0xffffffffu, rs, 1);
            rs += __shfl_xor_sync(0xffffffffu, rs, 2);
            if (tg == 0) s_rs[row][warp_n] = rs;
        }
    __syncthreads();
    g_rs[(size_t)bc * CC + tid] = s_rs[tid][0] + s_rs[tid][1];
}

// ---------------------------------------------------------------------------
// out = (A @ V_c + Q @ S_c) / d, split -> at_hi/at_lo (Q@S skipped for c==0)
// ---------------------------------------------------------------------------
__global__ __launch_bounds__(128, 2) void gemm_out_kernel()
{
    extern __shared__ char sm[];
    uint32_t su = smem_u32(sm);
    int n0 = blockIdx.x * 128;
    int bc = blockIdx.y, b = bc / NCH, c = bc % NCH;

    float acc[4][8][4];
    ZERO_ACC(acc);
    gemm_block(acc, su,
               A_hi + (size_t)bc * CC * CC, A_lo + (size_t)bc * CC * CC,
               vT_hi + ((size_t)b * EE + n0) * TT + (size_t)c * CC,
               vT_lo + ((size_t)b * EE + n0) * TT + (size_t)c * CC,
               CC, TT, 4);
    if (c != 0) {
        size_t qbase = ((size_t)b * TT + (size_t)c * CC) * EE;
        gemm_block(acc, su,
                   q_hi + qbase, q_lo + qbase,
                   S_hi + (size_t)bc * EE * EE + (size_t)n0 * EE,
                   S_lo + (size_t)bc * EE * EE + (size_t)n0 * EE,
                   EE, EE, 16);
    }

    EPI_VARS;
    (void)tid; (void)lane;
#pragma unroll
    for (int mt = 0; mt < 4; mt++)
#pragma unroll
        for (int h = 0; h < 2; h++) {
            int row = warp_m * 64 + mt * 16 + h * 8 + g;
            float d = fmaxf(g_rs[(size_t)bc * CC + row] + g_dz[(size_t)bc * CC + row], EPSV);
            float inv = 1.0f / d;
            size_t ob = ((size_t)b * TT + (size_t)c * CC + row) * EE + n0;
#pragma unroll
            for (int nt = 0; nt < 8; nt++) {
                int col = warp_n * 64 + nt * 8 + tg * 2;
                uint32_t hi, lo;
                split_pair(acc[mt][nt][2 * h] * inv, acc[mt][nt][2 * h + 1] * inv, hi, lo);
                *(uint32_t*)&at_hi[ob + col] = hi;
                *(uint32_t*)&at_lo[ob + col] = lo;
            }
        }
}

// ---------------------------------------------------------------------------
// output projection -> d_out
// ---------------------------------------------------------------------------
__global__ __launch_bounds__(128, 2) void gemm_oproj_kernel(
    const float* __restrict__ ob_bias, float* __restrict__ outp)
{
    extern __shared__ char sm[];
    uint32_t su = smem_u32(sm);
    int m0 = blockIdx.x * 128, n0 = blockIdx.y * 128;

    float acc[4][8][4];
    ZERO_ACC(acc);
    gemm_block(acc, su,
               at_hi + (size_t)m0 * EE, at_lo + (size_t)m0 * EE,
               w_hi + (size_t)3 * EE * EE + (size_t)n0 * EE,
               w_lo + (size_t)3 * EE * EE + (size_t)n0 * EE,
               EE, EE, 16);

    EPI_VARS;
    (void)tid; (void)lane;
#pragma unroll
    for (int mt = 0; mt < 4; mt++)
#pragma unroll
        for (int h = 0; h < 2; h++) {
            int row = m0 + warp_m * 64 + mt * 16 + h * 8 + g;
#pragma unroll
            for (int nt = 0; nt < 8; nt++) {
                int col = n0 + warp_n * 64 + nt * 8 + tg * 2;
                float2 o;
                o.x = acc[mt][nt][2 * h] + ob_bias[col];
                o.y = acc[mt][nt][2 * h + 1] + ob_bias[col + 1];
                *(float2*)&outp[(size_t)row * EE + col] = o;
            }
        }
}

// ---------------------------------------------------------------------------
// conversion / elementwise kernels
// ---------------------------------------------------------------------------
__global__ __launch_bounds__(256) void conv_w_kernel(
    const float* __restrict__ qw, const float* __restrict__ kw,
    const float* __restrict__ vw, const float* __restrict__ ow)
{
    size_t idx = (size_t)blockIdx.x * 256 + threadIdx.x;
    if (idx >= (size_t)4 * EE * EE) return;
    int which = (int)(idx / ((size_t)EE * EE));
    size_t rem = idx % ((size_t)EE * EE);
    const float* w = (which == 0) ? qw : (which == 1) ? kw : (which == 2) ? vw : ow;
    float x = w[rem];
    __nv_bfloat16 h = __float2bfloat16(x);
    w_hi[idx] = h;
    w_lo[idx] = __float2bfloat16(x - __bfloat162float(h));
}

// x (B,E,T) fp32 -> xT (B,T,E) bf16 split
__global__ __launch_bounds__(256) void conv_xT_kernel(const float* __restrict__ x)
{
    __shared__ float ts[32][33];
    int b = blockIdx.z;
    int t0 = blockIdx.x * 32, e0 = blockIdx.y * 32;
    int tx = threadIdx.x, ty = threadIdx.y;  // (32,8)
    const float* xb = x + (size_t)b * EE * TT;
#pragma unroll
    for (int i = 0; i < 4; i++)
        ts[ty + i * 8][tx] = xb[(size_t)(e0 + ty + i * 8) * TT + t0 + tx];
    __syncthreads();
    size_t ob = (size_t)b * TT * EE;
#pragma unroll
    for (int i = 0; i < 4; i++) {
        float val = ts[tx][ty + i * 8];
        __nv_bfloat16 h = __float2bfloat16(val);
        size_t o = ob + (size_t)(t0 + ty + i * 8) * EE + e0 + tx;
        xT_hi[o] = h;
        xT_lo[o] = __float2bfloat16(val - __bfloat162float(h));
    }
}

// q softmax + split
__global__ __launch_bounds__(128) void act_kernel()
{
    int bt = blockIdx.x;
    int tid = threadIdx.x;
    size_t base = (size_t)bt * EE;
    __shared__ float sred[4];

    float qv[4];
#pragma unroll
    for (int u = 0; u < 4; u++) qv[u] = g_q[base + tid + u * 128];
    float m = fmaxf(fmaxf(qv[0], qv[1]), fmaxf(qv[2], qv[3]));
#pragma unroll
    for (int o = 16; o; o >>= 1) m = fmaxf(m, __shfl_xor_sync(0xffffffffu, m, o));
    if ((tid & 31) == 0) sred[tid >> 5] = m;
    __syncthreads();
    m = fmaxf(fmaxf(sred[0], sred[1]), fmaxf(sred[2], sred[3]));
    __syncthreads();
    float s = 0.f;
#pragma unroll
    for (int u = 0; u < 4; u++) { qv[u] = expf(qv[u] - m); s += qv[u]; }
#pragma unroll
    for (int o = 16; o; o >>= 1) s += __shfl_xor_sync(0xffffffffu, s, o);
    if ((tid & 31) == 0) sred[tid >> 5] = s;
    __syncthreads();
    s = sred[0] + sred[1] + sred[2] + sred[3];
    float scale = INV_SQRT_E / s;
#pragma unroll
    for (int u = 0; u < 4; u++) {
        size_t idx = base + tid + u * 128;
        float val = qv[u] * scale;
        __nv_bfloat16 h = __float2bfloat16(val);
        q_hi[idx] = h;
        q_lo[idx] = __float2bfloat16(val - __bfloat162float(h));
    }
}

__global__ __launch_bounds__(128) void zprefix_kernel()
{
    int idx = blockIdx.x * blockDim.x + threadIdx.x;
    if (idx >= BB * EE) return;
    int b = idx / EE, off = idx % EE;
    float run = 0.f;
    float* p = g_z + (size_t)b * NCH * EE + off;
#pragma unroll
    for (int c = 0; c < NCH; c++) {
        float tmp = *p; *p = run; run += tmp; p += EE;
    }
}

// dz[b,c,i] = sum_e q[b, c*128+i, e] * z_excl[b,c,e]   (q from split)
__global__ __launch_bounds__(256) void dz_kernel()
{
    int bc = blockIdx.x;
    int b = bc / NCH, c = bc % NCH;
    int w = threadIdx.x >> 5, lane = threadIdx.x & 31;
    const float* z = g_z + (size_t)bc * EE;
#pragma unroll
    for (int it = 0; it < 16; it++) {
        int i = it * 8 + w;
        size_t qrow = ((size_t)b * TT + (size_t)c * CC + i) * EE;
        float s = 0.f;
#pragma unroll 4
        for (int j = lane; j < EE; j += 32) {
            float qv = __bfloat162float(q_hi[qrow + j]) + __bfloat162float(q_lo[qrow + j]);
            s += qv * z[j];
        }
#pragma unroll
        for (int o = 16; o; o >>= 1) s += __shfl_xor_sync(0xffffffffu, s, o);
        if (lane == 0) g_dz[(size_t)bc * CC + i] = s;
    }
}

// ---------------------------------------------------------------------------
extern "C" void kernel_launch(void* const* d_in, const int* in_sizes, int n_in,
                              void* d_out, int out_size)
{
    const float* x    = (const float*)d_in[0];
    const float* toep = (const float*)d_in[1];
    const float* qw   = (const float*)d_in[2];
    const float* qb   = (const float*)d_in[3];
    const float* kw   = (const float*)d_in[4];
    const float* kb   = (const float*)d_in[5];
    const float* vw   = (const float*)d_in[6];
    const float* vb   = (const float*)d_in[7];
    const float* ow   = (const float*)d_in[8];
    const float* ob   = (const float*)d_in[9];
    float* out = (float*)d_out;

    static cudaStream_t s_aux = nullptr;
    static cudaEvent_t ev_fork = nullptr, ev_kv = nullptr, ev_join = nullptr;
    static int attr_done = 0;
    if (!attr_done) {
        cudaFuncSetAttribute(gemm_proj_kernel,  cudaFuncAttributeMaxDynamicSharedMemorySize, SMEM_BYTES);
        cudaFuncSetAttribute(gemm_hscan_kernel, cudaFuncAttributeMaxDynamicSharedMemorySize, SMEM_BYTES);
        cudaFuncSetAttribute(gemm_qk_kernel,    cudaFuncAttributeMaxDynamicSharedMemorySize, SMEM_BYTES);
        cudaFuncSetAttribute(gemm_out_kernel,   cudaFuncAttributeMaxDynamicSharedMemorySize, SMEM_BYTES);
        cudaFuncSetAttribute(gemm_oproj_kernel, cudaFuncAttributeMaxDynamicSharedMemorySize, SMEM_BYTES);
        cudaStreamCreateWithFlags(&s_aux, cudaStreamNonBlocking);
        cudaEventCreateWithFlags(&ev_fork, cudaEventDisableTiming);
        cudaEventCreateWithFlags(&ev_kv,   cudaEventDisableTiming);
        cudaEventCreateWithFlags(&ev_join, cudaEventDisableTiming);
        attr_done = 1;
    }

    // main: conversions
    conv_w_kernel<<<(int)(((size_t)4 * EE * EE + 255) / 256), 256>>>(qw, kw, vw, ow);
    conv_xT_kernel<<<dim3(TT / 32, EE / 32, BB), dim3(32, 8)>>>(x);

    // fork after conversions: aux does the q pipeline, main does k/v + hscan
    cudaEventRecord(ev_fork, 0);
    cudaStreamWaitEvent(s_aux, ev_fork, 0);

    // aux: q projection + softmax/split
    gemm_proj_kernel<<<dim3(BB * TT / 128, EE / 128, 1), 128, SMEM_BYTES, s_aux>>>(
        qb, kb, vb, toep, 0);
    act_kernel<<<BB * TT, 128, 0, s_aux>>>();

    // main: k/v projections, then state scan
    gemm_proj_kernel<<<dim3(BB * TT / 128, EE / 128, 2), 128, SMEM_BYTES>>>(
        qb, kb, vb, toep, 1);
    cudaEventRecord(ev_kv, 0);
    gemm_hscan_kernel<<<dim3(EE / 128, EE / 128, BB), 128, SMEM_BYTES>>>();

    // aux (needs k/v results): zprefix, qk, dz
    cudaStreamWaitEvent(s_aux, ev_kv, 0);
    zprefix_kernel<<<(BB * EE + 127) / 128, 128, 0, s_aux>>>();
    gemm_qk_kernel<<<BB * NCH, 128, SMEM_BYTES, s_aux>>>();
    dz_kernel<<<BB * NCH, 256, 0, s_aux>>>();
    cudaEventRecord(ev_join, s_aux);

    // main: join, then out + oproj
    cudaStreamWaitEvent(0, ev_join, 0);
    gemm_out_kernel<<<dim3(EE / 128, BB * NCH), 128, SMEM_BYTES>>>();
    gemm_oproj_kernel<<<dim3(BB * TT / 128, EE / 128), 128, SMEM_BYTES>>>(ob, out);
}

// round 17
// speedup vs baseline: 1.3170x; 1.0201x over previous
#include <cuda_runtime.h>
#include <cuda_bf16.h>
#include <math.h>
#include <stdint.h>

#define BB 8
#define TT 2048
#define EE 512
#define CC 128
#define NCH 16
#define EPSV 1e-3f
#define INV_SQRT_E 0.04419417382415922f  // 512^-0.5

// ---------------------------------------------------------------------------
// scratch (device globals; no cudaMalloc allowed)
// ---------------------------------------------------------------------------
static __device__ float g_q[(size_t)BB * TT * EE];   // fp32 q (pre-softmax)

static __device__ __nv_bfloat16 xT_hi[(size_t)BB * TT * EE];
static __device__ __nv_bfloat16 xT_lo[(size_t)BB * TT * EE];
static __device__ __nv_bfloat16 w_hi[(size_t)4 * EE * EE];  // q,k,v,o
static __device__ __nv_bfloat16 w_lo[(size_t)4 * EE * EE];
static __device__ __nv_bfloat16 q_hi[(size_t)BB * TT * EE];
static __device__ __nv_bfloat16 q_lo[(size_t)BB * TT * EE];
static __device__ __nv_bfloat16 k_hi[(size_t)BB * TT * EE];
static __device__ __nv_bfloat16 k_lo[(size_t)BB * TT * EE];
static __device__ __nv_bfloat16 kT_hi[(size_t)BB * EE * TT];
static __device__ __nv_bfloat16 kT_lo[(size_t)BB * EE * TT];
static __device__ __nv_bfloat16 vT_hi[(size_t)BB * EE * TT];
static __device__ __nv_bfloat16 vT_lo[(size_t)BB * EE * TT];
static __device__ __nv_bfloat16 S_hi[(size_t)BB * NCH * EE * EE]; // exclusive-prefix states
static __device__ __nv_bfloat16 S_lo[(size_t)BB * NCH * EE * EE];
static __device__ __nv_bfloat16 A_hi[(size_t)BB * NCH * CC * CC]; // masked QK^T
static __device__ __nv_bfloat16 A_lo[(size_t)BB * NCH * CC * CC];
static __device__ __nv_bfloat16 at_hi[(size_t)BB * TT * EE];      // attn output (split)
static __device__ __nv_bfloat16 at_lo[(size_t)BB * TT * EE];

static __device__ float g_z[(size_t)BB * NCH * EE];   // key colsums -> exclusive prefix
static __device__ float g_rs[(size_t)BB * NCH * CC];  // rowsum of masked A
static __device__ float g_dz[(size_t)BB * NCH * CC];  // q . z_excl

// ---------------------------------------------------------------------------
// helpers
// ---------------------------------------------------------------------------
__device__ __forceinline__ uint32_t smem_u32(const void* p) {
    uint32_t a;
    asm("{ .reg .u64 t; cvta.to.shared.u64 t, %1; cvt.u32.u64 %0, t; }" : "=r"(a) : "l"(p));
    return a;
}

__device__ __forceinline__ void ldm4(uint32_t* r, uint32_t addr) {
    asm volatile("ldmatrix.sync.aligned.m8n8.x4.shared.b16 {%0,%1,%2,%3}, [%4];"
                 : "=r"(r[0]), "=r"(r[1]), "=r"(r[2]), "=r"(r[3]) : "r"(addr));
}

__device__ __forceinline__ void mma16816(float* c, const uint32_t* a, uint32_t b0, uint32_t b1) {
    asm volatile(
        "mma.sync.aligned.m16n8k16.row.col.f32.bf16.bf16.f32 "
        "{%0,%1,%2,%3}, {%4,%5,%6,%7}, {%8,%9}, {%0,%1,%2,%3};"
        : "+f"(c[0]), "+f"(c[1]), "+f"(c[2]), "+f"(c[3])
        : "r"(a[0]), "r"(a[1]), "r"(a[2]), "r"(a[3]), "r"(b0), "r"(b1));
}

__device__ __forceinline__ void cpa16(uint32_t dst, const void* src) {
    asm volatile("cp.async.cg.shared.global [%0], [%1], 16;" :: "r"(dst), "l"(src));
}

__device__ __forceinline__ void split_pair(float x, float y, uint32_t& hi, uint32_t& lo) {
    __nv_bfloat16 hx = __float2bfloat16(x), hy = __float2bfloat16(y);
    __nv_bfloat16 lx = __float2bfloat16(x - __bfloat162float(hx));
    __nv_bfloat16 ly = __float2bfloat16(y - __bfloat162float(hy));
    hi = (uint32_t)__bfloat16_as_ushort(hx) | ((uint32_t)__bfloat16_as_ushort(hy) << 16);
    lo = (uint32_t)__bfloat16_as_ushort(lx) | ((uint32_t)__bfloat16_as_ushort(ly) << 16);
}

// ---------------------------------------------------------------------------
// block GEMM (128x128): C[m,n] += sum_k (Ahi+Alo)[m,k]*(Bhi+Blo)[n,k]
// BK=32, 3-stage cp.async pipeline, 128 threads, 4 warps (2m x 2n), warp 64x64
// ---------------------------------------------------------------------------
#define NSTAGE 3
#define STAGE_BYTES 32768
#define SMEM_BYTES (NSTAGE * STAGE_BYTES)

__device__ __forceinline__ void stage_load(
    uint32_t su, int buf,
    const __nv_bfloat16* __restrict__ ah, const __nv_bfloat16* __restrict__ al,
    const __nv_bfloat16* __restrict__ bh, const __nv_bfloat16* __restrict__ bl,
    int lda, int ldb, int kofs)
{
    uint32_t sb = su + (uint32_t)buf * STAGE_BYTES;
    int tid = threadIdx.x;
#pragma unroll
    for (int u = 0; u < 4; u++) {
        int ch = tid + u * 128;          // 0..511
        int row = ch >> 2, c16 = ch & 3; // 128 rows x 4 16B-chunks
        uint32_t so = (uint32_t)(row * 64 + ((c16 ^ ((row >> 1) & 3)) * 16));
        size_t goa = (size_t)row * lda + kofs + c16 * 8;
        size_t gob = (size_t)row * ldb + kofs + c16 * 8;
        cpa16(sb + so, ah + goa);
        cpa16(sb + 8192 + so, al + goa);
        cpa16(sb + 16384 + so, bh + gob);
        cpa16(sb + 24576 + so, bl + gob);
    }
    asm volatile("cp.async.commit_group;" ::: "memory");
}

// per-stage MMA compute on buffer at sb (lane constants recomputed; inlined,
// ptxas hoists the invariant parts).
__device__ __forceinline__ void compute_stage(float (&acc)[4][8][4], uint32_t sb)
{
    const int tid = threadIdx.x;
    const int lane = tid & 31, wid = tid >> 5;
    const int warp_m = wid >> 1, warp_n = wid & 1;
    const int q = lane >> 3, r8 = lane & 7;
    const int a_rowoff = warp_m * 64 + (q & 1) * 8 + r8;
    const int a_kcadd  = q >> 1;
    const int b_nbase  = warp_n * 64 + (q >> 1) * 8 + r8;
    const int b_kcadd  = q & 1;
    const int xor3a = (a_rowoff >> 1) & 3;
    const int xor3b = (b_nbase >> 1) & 3;
    uint32_t a_base = sb + (uint32_t)(a_rowoff * 64);
    uint32_t b_base = sb + 16384u + (uint32_t)(b_nbase * 64);
#pragma unroll
    for (int ks = 0; ks < 2; ks++) {
        uint32_t Ah[4][4], Al[4][4];
        uint32_t a_ch = (uint32_t)((((ks * 2 + a_kcadd) ^ xor3a) & 3) * 16);
#pragma unroll
        for (int mt = 0; mt < 4; mt++) {
            uint32_t addr = a_base + (uint32_t)(mt * 1024) + a_ch;
            ldm4(Ah[mt], addr);
            ldm4(Al[mt], addr + 8192u);
        }
        uint32_t b_ch = (uint32_t)((((ks * 2 + b_kcadd) ^ xor3b) & 3) * 16);
#pragma unroll
        for (int nt = 0; nt < 4; nt++) {
            uint32_t Bh[4], Bl[4];
            uint32_t baddr = b_base + (uint32_t)(nt * 1024) + b_ch;
            ldm4(Bh, baddr);
            ldm4(Bl, baddr + 8192u);
#pragma unroll
            for (int mt = 0; mt < 4; mt++) {
#pragma unroll
                for (int h = 0; h < 2; h++) {
                    float* c = acc[mt][nt * 2 + h];
                    mma16816(c, Ah[mt], Bh[2 * h], Bh[2 * h + 1]);
                    mma16816(c, Ah[mt], Bl[2 * h], Bl[2 * h + 1]);
                    mma16816(c, Al[mt], Bh[2 * h], Bh[2 * h + 1]);
                }
            }
        }
    }
}

__device__ __forceinline__ void gemm_prologue(
    uint32_t su,
    const __nv_bfloat16* __restrict__ ah, const __nv_bfloat16* __restrict__ al,
    const __nv_bfloat16* __restrict__ bh, const __nv_bfloat16* __restrict__ bl,
    int lda, int ldb, int nk)
{
#pragma unroll
    for (int s = 0; s < NSTAGE - 1; s++) {
        if (s < nk) stage_load(su, s, ah, al, bh, bl, lda, ldb, s * 32);
        else asm volatile("cp.async.commit_group;" ::: "memory");
    }
}

__device__ __forceinline__ void gemm_body(
    float (&acc)[4][8][4], uint32_t su,
    const __nv_bfloat16* __restrict__ ah, const __nv_bfloat16* __restrict__ al,
    const __nv_bfloat16* __restrict__ bh, const __nv_bfloat16* __restrict__ bl,
    int lda, int ldb, int nk)
{
    for (int kc = 0; kc < nk; kc++) {
        asm volatile("cp.async.wait_group %0;" :: "n"(NSTAGE - 2) : "memory");
        __syncthreads();
        int pf = kc + NSTAGE - 1;
        if (pf < nk) stage_load(su, pf % NSTAGE, ah, al, bh, bl, lda, ldb, pf * 32);
        else asm volatile("cp.async.commit_group;" ::: "memory");

        compute_stage(acc, su + (uint32_t)(kc % NSTAGE) * STAGE_BYTES);
    }
}

__device__ __forceinline__ void gemm_block(
    float (&acc)[4][8][4], uint32_t su,
    const __nv_bfloat16* __restrict__ ah, const __nv_bfloat16* __restrict__ al,
    const __nv_bfloat16* __restrict__ bh, const __nv_bfloat16* __restrict__ bl,
    int lda, int ldb, int nk)
{
    __syncthreads();
    gemm_prologue(su, ah, al, bh, bl, lda, ldb, nk);
    gemm_body(acc, su, ah, al, bh, bl, lda, ldb, nk);
    __syncthreads();
}

#define ZERO_ACC(acc) do { \
    _Pragma("unroll") for (int _i = 0; _i < 4; _i++) \
    _Pragma("unroll") for (int _j = 0; _j < 8; _j++) \
    _Pragma("unroll") for (int _l = 0; _l < 4; _l++) acc[_i][_j][_l] = 0.f; \
} while (0)

// rows = warp_m*64 + mt*16 + h*8 + g; cols = warp_n*64 + nt*8 + tg*2
#define EPI_VARS \
    const int tid = threadIdx.x; \
    const int lane = tid & 31, wid = tid >> 5; \
    const int warp_m = wid >> 1, warp_n = wid & 1; \
    const int g = lane >> 2, tg = lane & 3;

#define TPAD 136   // padded row length (elems) for transpose buffer (16B-mult)

// ---------------------------------------------------------------------------
// q/k/v projections: D[t,j] = sum_e xT[t,e] * W[j,e] + bias
// which = which_base + blockIdx.z:
//   0 (q): fp32 row-major -> g_q
//   1 (k): exp -> split row-major, transpose -> kT, colsum -> g_z
//   2 (v): *toep[t] -> transpose -> vT
// ---------------------------------------------------------------------------
__global__ __launch_bounds__(128, 2) void gemm_proj_kernel(
    const float* __restrict__ qb, const float* __restrict__ kb,
    const float* __restrict__ vb, const float* __restrict__ toep, int which_base)
{
    extern __shared__ char sm[];
    __shared__ float zred[2][128];
    uint32_t su = smem_u32(sm);
    int m0 = blockIdx.x * 128, n0 = blockIdx.y * 128;
    int which = which_base + blockIdx.z;

    float acc[4][8][4];
    ZERO_ACC(acc);
    gemm_block(acc, su,
               xT_hi + (size_t)m0 * EE, xT_lo + (size_t)m0 * EE,
               w_hi + (size_t)which * EE * EE + (size_t)n0 * EE,
               w_lo + (size_t)which * EE * EE + (size_t)n0 * EE,
               EE, EE, 16);

    EPI_VARS;
    const int b = m0 / TT, t0g = m0 % TT;
    __nv_bfloat16* buf = (__nv_bfloat16*)sm;   // reuse gemm smem for transpose

    if (which == 0) {
#pragma unroll
        for (int mt = 0; mt < 4; mt++)
#pragma unroll
            for (int h = 0; h < 2; h++) {
                int row = m0 + warp_m * 64 + mt * 16 + h * 8 + g;
#pragma unroll
                for (int nt = 0; nt < 8; nt++) {
                    int col = n0 + warp_n * 64 + nt * 8 + tg * 2;
                    float2 o;
                    o.x = acc[mt][nt][2 * h] + qb[col];
                    o.y = acc[mt][nt][2 * h + 1] + qb[col + 1];
                    *(float2*)&g_q[(size_t)row * EE + col] = o;
                }
            }
        return;
    }

    if (which == 1) {
        float cs[16];
#pragma unroll
        for (int i = 0; i < 16; i++) cs[i] = 0.f;
#pragma unroll
        for (int mt = 0; mt < 4; mt++)
#pragma unroll
            for (int h = 0; h < 2; h++) {
                int row = warp_m * 64 + mt * 16 + h * 8 + g;
#pragma unroll
                for (int nt = 0; nt < 8; nt++) {
                    int col = warp_n * 64 + nt * 8 + tg * 2;
                    float v0 = expf(acc[mt][nt][2 * h]     + kb[n0 + col]);
                    float v1 = expf(acc[mt][nt][2 * h + 1] + kb[n0 + col + 1]);
                    acc[mt][nt][2 * h] = v0;
                    acc[mt][nt][2 * h + 1] = v1;
                    cs[nt * 2] += v0;
                    cs[nt * 2 + 1] += v1;
                    uint32_t hi, lo;
                    split_pair(v0, v1, hi, lo);
                    *(uint32_t*)&k_hi[(size_t)(m0 + row) * EE + n0 + col] = hi;
                    *(uint32_t*)&k_lo[(size_t)(m0 + row) * EE + n0 + col] = lo;
                }
            }
#pragma unroll
        for (int i = 0; i < 16; i++) {
            cs[i] += __shfl_xor_sync(0xffffffffu, cs[i], 4);
            cs[i] += __shfl_xor_sync(0xffffffffu, cs[i], 8);
            cs[i] += __shfl_xor_sync(0xffffffffu, cs[i], 16);
        }
        if (g == 0) {
#pragma unroll
            for (int nt = 0; nt < 8; nt++) {
                int col = warp_n * 64 + nt * 8 + tg * 2;
                zred[warp_m][col] = cs[nt * 2];
                zred[warp_m][col + 1] = cs[nt * 2 + 1];
            }
        }
    } else {
#pragma unroll
        for (int mt = 0; mt < 4; mt++)
#pragma unroll
            for (int h = 0; h < 2; h++) {
                int row = warp_m * 64 + mt * 16 + h * 8 + g;
                float tw = toep[t0g + row];
#pragma unroll
                for (int nt = 0; nt < 8; nt++) {
                    int col = warp_n * 64 + nt * 8 + tg * 2;
                    acc[mt][nt][2 * h]     = (acc[mt][nt][2 * h]     + vb[n0 + col]) * tw;
                    acc[mt][nt][2 * h + 1] = (acc[mt][nt][2 * h + 1] + vb[n0 + col + 1]) * tw;
                }
            }
    }

    __nv_bfloat16* dsth = (which == 1) ? kT_hi : vT_hi;
    __nv_bfloat16* dstl = (which == 1) ? kT_lo : vT_lo;

    // pass 1: hi transpose
#pragma unroll
    for (int mt = 0; mt < 4; mt++)
#pragma unroll
        for (int h = 0; h < 2; h++) {
            int row = warp_m * 64 + mt * 16 + h * 8 + g;
#pragma unroll
            for (int nt = 0; nt < 8; nt++) {
                int col = warp_n * 64 + nt * 8 + tg * 2;
                buf[(size_t)col * TPAD + row] = __float2bfloat16(acc[mt][nt][2 * h]);
                buf[(size_t)(col + 1) * TPAD + row] = __float2bfloat16(acc[mt][nt][2 * h + 1]);
            }
        }
    __syncthreads();
    if (which == 1) {
        int bc = b * NCH + t0g / CC;
        g_z[(size_t)bc * EE + n0 + tid] = zred[0][tid] + zred[1][tid];
    }
    {
        const uint4* src = (const uint4*)(buf + (size_t)tid * TPAD);
        uint4* dst = (uint4*)(dsth + ((size_t)b * EE + n0 + tid) * TT + t0g);
#pragma unroll
        for (int i = 0; i < 16; i++) dst[i] = src[i];
    }
    __syncthreads();
    // pass 2: lo transpose
#pragma unroll
    for (int mt = 0; mt < 4; mt++)
#pragma unroll
        for (int h = 0; h < 2; h++) {
            int row = warp_m * 64 + mt * 16 + h * 8 + g;
#pragma unroll
            for (int nt = 0; nt < 8; nt++) {
                int col = warp_n * 64 + nt * 8 + tg * 2;
                float v0 = acc[mt][nt][2 * h], v1 = acc[mt][nt][2 * h + 1];
                buf[(size_t)col * TPAD + row] =
                    __float2bfloat16(v0 - __bfloat162float(__float2bfloat16(v0)));
                buf[(size_t)(col + 1) * TPAD + row] =
                    __float2bfloat16(v1 - __bfloat162float(__float2bfloat16(v1)));
            }
        }
    __syncthreads();
    {
        const uint4* src = (const uint4*)(buf + (size_t)tid * TPAD);
        uint4* dst = (uint4*)(dstl + ((size_t)b * EE + n0 + tid) * TT + t0g);
#pragma unroll
        for (int i = 0; i < 16; i++) dst[i] = src[i];
    }
}

// ---------------------------------------------------------------------------
// fused chunk-state scan (128x128 tiles): per (m0, n0, b), chunks c = 0..15;
// prefetch chunk-c stages BEFORE storing S_c (hides the store); skip the
// last chunk's GEMM and the S_0 store (S_0 == 0; out kernel skips c==0 Q@S).
// ---------------------------------------------------------------------------
__global__ __launch_bounds__(128, 2) void gemm_hscan_kernel()
{
    extern __shared__ char sm[];
    uint32_t su = smem_u32(sm);
    int m0 = blockIdx.x * 128, n0 = blockIdx.y * 128;
    int b = blockIdx.z;

    float acc[4][8][4];
    ZERO_ACC(acc);
    EPI_VARS;
    (void)tid; (void)lane;

    for (int c = 0; c < NCH; c++) {
        int bc = b * NCH + c;
        const __nv_bfloat16* ah = vT_hi + ((size_t)b * EE + m0) * TT + (size_t)c * CC;
        const __nv_bfloat16* al = vT_lo + ((size_t)b * EE + m0) * TT + (size_t)c * CC;
        const __nv_bfloat16* bh = kT_hi + ((size_t)b * EE + n0) * TT + (size_t)c * CC;
        const __nv_bfloat16* bl = kT_lo + ((size_t)b * EE + n0) * TT + (size_t)c * CC;
        bool do_gemm = (c < NCH - 1);

        __syncthreads();
        if (do_gemm) gemm_prologue(su, ah, al, bh, bl, TT, TT, 4);

        if (c > 0) {
            __nv_bfloat16* Sh = S_hi + (size_t)bc * EE * EE;
            __nv_bfloat16* Sl = S_lo + (size_t)bc * EE * EE;
#pragma unroll
            for (int mt = 0; mt < 4; mt++)
#pragma unroll
                for (int h = 0; h < 2; h++) {
                    int row = m0 + warp_m * 64 + mt * 16 + h * 8 + g;
#pragma unroll
                    for (int nt = 0; nt < 8; nt++) {
                        int col = n0 + warp_n * 64 + nt * 8 + tg * 2;
                        uint32_t hi, lo;
                        split_pair(acc[mt][nt][2 * h], acc[mt][nt][2 * h + 1], hi, lo);
                        *(uint32_t*)&Sh[(size_t)row * EE + col] = hi;
                        *(uint32_t*)&Sl[(size_t)row * EE + col] = lo;
                    }
                }
        }
        if (do_gemm) gemm_body(acc, su, ah, al, bh, bl, TT, TT, 4);
    }
}

// ---------------------------------------------------------------------------
// A = causal-mask(Q K^T): rowsum -> g_rs, split bf16 -> A_hi/A_lo
// ---------------------------------------------------------------------------
__global__ __launch_bounds__(128, 2) void gemm_qk_kernel()
{
    extern __shared__ char sm[];
    __shared__ float s_rs[128][2];
    uint32_t su = smem_u32(sm);
    int bc = blockIdx.x, b = bc / NCH, c = bc % NCH;
    size_t base = ((size_t)b * TT + (size_t)c * CC) * EE;

    float acc[4][8][4];
    ZERO_ACC(acc);
    gemm_block(acc, su, q_hi + base, q_lo + base, k_hi + base, k_lo + base, EE, EE, 16);

    EPI_VARS;
    (void)lane;
    __nv_bfloat16* Ah = A_hi + (size_t)bc * CC * CC;
    __nv_bfloat16* Al = A_lo + (size_t)bc * CC * CC;
#pragma unroll
    for (int mt = 0; mt < 4; mt++)
#pragma unroll
        for (int h = 0; h < 2; h++) {
            int row = warp_m * 64 + mt * 16 + h * 8 + g;
            float rs = 0.f;
#pragma unroll
            for (int nt = 0; nt < 8; nt++) {
                int col = warp_n * 64 + nt * 8 + tg * 2;
                float v0 = acc[mt][nt][2 * h], v1 = acc[mt][nt][2 * h + 1];
                if (col > row) v0 = 0.f;
                if (col + 1 > row) v1 = 0.f;
                rs += v0 + v1;
                uint32_t hi, lo;
                split_pair(v0, v1, hi, lo);
                *(uint32_t*)&Ah[(size_t)row * CC + col] = hi;
                *(uint32_t*)&Al[(size_t)row * CC + col] = lo;
            }
            rs += __shfl_xor_sync(0xffffffffu, rs, 1);
            rs += __shfl_xor_sync(0xffffffffu, rs, 2);
            if (tg == 0) s_rs[row][warp_n] = rs;
        }
    __syncthreads();
    g_rs[(size_t)bc * CC + tid] = s_rs[tid][0] + s_rs[tid][1];
}

// ---------------------------------------------------------------------------
// out = (A @ V_c + Q @ S_c) / d, split -> at_hi/at_lo.
// Single fused 20-step pipeline: steps 0-3 load (A, vT), steps 4-19 load
// (q, S) -- no mid-phase pipeline drain. Q@S skipped for c==0 (S_0 == 0).
// ---------------------------------------------------------------------------
__global__ __launch_bounds__(128, 2) void gemm_out_kernel()
{
    extern __shared__ char sm[];
    uint32_t su = smem_u32(sm);
    int n0 = blockIdx.x * 128;
    int bc = blockIdx.y, b = bc / NCH, c = bc % NCH;

    const __nv_bfloat16* a1h = A_hi + (size_t)bc * CC * CC;
    const __nv_bfloat16* a1l = A_lo + (size_t)bc * CC * CC;
    const __nv_bfloat16* b1h = vT_hi + ((size_t)b * EE + n0) * TT + (size_t)c * CC;
    const __nv_bfloat16* b1l = vT_lo + ((size_t)b * EE + n0) * TT + (size_t)c * CC;
    size_t qbase = ((size_t)b * TT + (size_t)c * CC) * EE;
    const __nv_bfloat16* a2h = q_hi + qbase;
    const __nv_bfloat16* a2l = q_lo + qbase;
    const __nv_bfloat16* b2h = S_hi + (size_t)bc * EE * EE + (size_t)n0 * EE;
    const __nv_bfloat16* b2l = S_lo + (size_t)bc * EE * EE + (size_t)n0 * EE;

    const int nk_total = (c != 0) ? 20 : 4;

    float acc[4][8][4];
    ZERO_ACC(acc);

    __syncthreads();
    // prologue: steps 0..NSTAGE-2 (all in phase 1 since nk_total >= 4 > 2)
#pragma unroll
    for (int s = 0; s < NSTAGE - 1; s++)
        stage_load(su, s, a1h, a1l, b1h, b1l, CC, TT, s * 32);

    for (int kc = 0; kc < nk_total; kc++) {
        asm volatile("cp.async.wait_group %0;" :: "n"(NSTAGE - 2) : "memory");
        __syncthreads();
        int pf = kc + NSTAGE - 1;
        if (pf < 4)
            stage_load(su, pf % NSTAGE, a1h, a1l, b1h, b1l, CC, TT, pf * 32);
        else if (pf < nk_total)
            stage_load(su, pf % NSTAGE, a2h, a2l, b2h, b2l, EE, EE, (pf - 4) * 32);
        else
            asm volatile("cp.async.commit_group;" ::: "memory");

        compute_stage(acc, su + (uint32_t)(kc % NSTAGE) * STAGE_BYTES);
    }
    __syncthreads();

    EPI_VARS;
    (void)tid; (void)lane;
#pragma unroll
    for (int mt = 0; mt < 4; mt++)
#pragma unroll
        for (int h = 0; h < 2; h++) {
            int row = warp_m * 64 + mt * 16 + h * 8 + g;
            float d = fmaxf(g_rs[(size_t)bc * CC + row] + g_dz[(size_t)bc * CC + row], EPSV);
            float inv = 1.0f / d;
            size_t ob = ((size_t)b * TT + (size_t)c * CC + row) * EE + n0;
#pragma unroll
            for (int nt = 0; nt < 8; nt++) {
                int col = warp_n * 64 + nt * 8 + tg * 2;
                uint32_t hi, lo;
                split_pair(acc[mt][nt][2 * h] * inv, acc[mt][nt][2 * h + 1] * inv, hi, lo);
                *(uint32_t*)&at_hi[ob + col] = hi;
                *(uint32_t*)&at_lo[ob + col] = lo;
            }
        }
}

// ---------------------------------------------------------------------------
// output projection -> d_out
// ---------------------------------------------------------------------------
__global__ __launch_bounds__(128, 2) void gemm_oproj_kernel(
    const float* __restrict__ ob_bias, float* __restrict__ outp)
{
    extern __shared__ char sm[];
    uint32_t su = smem_u32(sm);
    int m0 = blockIdx.x * 128, n0 = blockIdx.y * 128;

    float acc[4][8][4];
    ZERO_ACC(acc);
    gemm_block(acc, su,
               at_hi + (size_t)m0 * EE, at_lo + (size_t)m0 * EE,
               w_hi + (size_t)3 * EE * EE + (size_t)n0 * EE,
               w_lo + (size_t)3 * EE * EE + (size_t)n0 * EE,
               EE, EE, 16);

    EPI_VARS;
    (void)tid; (void)lane;
#pragma unroll
    for (int mt = 0; mt < 4; mt++)
#pragma unroll
        for (int h = 0; h < 2; h++) {
            int row = m0 + warp_m * 64 + mt * 16 + h * 8 + g;
#pragma unroll
            for (int nt = 0; nt < 8; nt++) {
                int col = n0 + warp_n * 64 + nt * 8 + tg * 2;
                float2 o;
                o.x = acc[mt][nt][2 * h] + ob_bias[col];
                o.y = acc[mt][nt][2 * h + 1] + ob_bias[col + 1];
                *(float2*)&outp[(size_t)row * EE + col] = o;
            }
        }
}

// ---------------------------------------------------------------------------
// conversion / elementwise kernels
// ---------------------------------------------------------------------------
__global__ __launch_bounds__(256) void conv_w_kernel(
    const float* __restrict__ qw, const float* __restrict__ kw,
    const float* __restrict__ vw, const float* __restrict__ ow)
{
    size_t idx = (size_t)blockIdx.x * 256 + threadIdx.x;
    if (idx >= (size_t)4 * EE * EE) return;
    int which = (int)(idx / ((size_t)EE * EE));
    size_t rem = idx % ((size_t)EE * EE);
    const float* w = (which == 0) ? qw : (which == 1) ? kw : (which == 2) ? vw : ow;
    float x = w[rem];
    __nv_bfloat16 h = __float2bfloat16(x);
    w_hi[idx] = h;
    w_lo[idx] = __float2bfloat16(x - __bfloat162float(h));
}

// x (B,E,T) fp32 -> xT (B,T,E) bf16 split
__global__ __launch_bounds__(256) void conv_xT_kernel(const float* __restrict__ x)
{
    __shared__ float ts[32][33];
    int b = blockIdx.z;
    int t0 = blockIdx.x * 32, e0 = blockIdx.y * 32;
    int tx = threadIdx.x, ty = threadIdx.y;  // (32,8)
    const float* xb = x + (size_t)b * EE * TT;
#pragma unroll
    for (int i = 0; i < 4; i++)
        ts[ty + i * 8][tx] = xb[(size_t)(e0 + ty + i * 8) * TT + t0 + tx];
    __syncthreads();
    size_t ob = (size_t)b * TT * EE;
#pragma unroll
    for (int i = 0; i < 4; i++) {
        float val = ts[tx][ty + i * 8];
        __nv_bfloat16 h = __float2bfloat16(val);
        size_t o = ob + (size_t)(t0 + ty + i * 8) * EE + e0 + tx;
        xT_hi[o] = h;
        xT_lo[o] = __float2bfloat16(val - __bfloat162float(h));
    }
}

// q softmax + split
__global__ __launch_bounds__(128) void act_kernel()
{
    int bt = blockIdx.x;
    int tid = threadIdx.x;
    size_t base = (size_t)bt * EE;
    __shared__ float sred[4];

    float qv[4];
#pragma unroll
    for (int u = 0; u < 4; u++) qv[u] = g_q[base + tid + u * 128];
    float m = fmaxf(fmaxf(qv[0], qv[1]), fmaxf(qv[2], qv[3]));
#pragma unroll
    for (int o = 16; o; o >>= 1) m = fmaxf(m, __shfl_xor_sync(0xffffffffu, m, o));
    if ((tid & 31) == 0) sred[tid >> 5] = m;
    __syncthreads();
    m = fmaxf(fmaxf(sred[0], sred[1]), fmaxf(sred[2], sred[3]));
    __syncthreads();
    float s = 0.f;
#pragma unroll
    for (int u = 0; u < 4; u++) { qv[u] = expf(qv[u] - m); s += qv[u]; }
#pragma unroll
    for (int o = 16; o; o >>= 1) s += __shfl_xor_sync(0xffffffffu, s, o);
    if ((tid & 31) == 0) sred[tid >> 5] = s;
    __syncthreads();
    s = sred[0] + sred[1] + sred[2] + sred[3];
    float scale = INV_SQRT_E / s;
#pragma unroll
    for (int u = 0; u < 4; u++) {
        size_t idx = base + tid + u * 128;
        float val = qv[u] * scale;
        __nv_bfloat16 h = __float2bfloat16(val);
        q_hi[idx] = h;
        q_lo[idx] = __float2bfloat16(val - __bfloat162float(h));
    }
}

__global__ __launch_bounds__(128) void zprefix_kernel()
{
    int idx = blockIdx.x * blockDim.x + threadIdx.x;
    if (idx >= BB * EE) return;
    int b = idx / EE, off = idx % EE;
    float run = 0.f;
    float* p = g_z + (size_t)b * NCH * EE + off;
#pragma unroll
    for (int c = 0; c < NCH; c++) {
        float tmp = *p; *p = run; run += tmp; p += EE;
    }
}

// dz[b,c,i] = sum_e q[b, c*128+i, e] * z_excl[b,c,e]   (q from split)
__global__ __launch_bounds__(256) void dz_kernel()
{
    int bc = blockIdx.x;
    int b = bc / NCH, c = bc % NCH;
    int w = threadIdx.x >> 5, lane = threadIdx.x & 31;
    const float* z = g_z + (size_t)bc * EE;
#pragma unroll
    for (int it = 0; it < 16; it++) {
        int i = it * 8 + w;
        size_t qrow = ((size_t)b * TT + (size_t)c * CC + i) * EE;
        float s = 0.f;
#pragma unroll 4
        for (int j = lane; j < EE; j += 32) {
            float qv = __bfloat162float(q_hi[qrow + j]) + __bfloat162float(q_lo[qrow + j]);
            s += qv * z[j];
        }
#pragma unroll
        for (int o = 16; o; o >>= 1) s += __shfl_xor_sync(0xffffffffu, s, o);
        if (lane == 0) g_dz[(size_t)bc * CC + i] = s;
    }
}

// ---------------------------------------------------------------------------
extern "C" void kernel_launch(void* const* d_in, const int* in_sizes, int n_in,
                              void* d_out, int out_size)
{
    const float* x    = (const float*)d_in[0];
    const float* toep = (const float*)d_in[1];
    const float* qw   = (const float*)d_in[2];
    const float* qb   = (const float*)d_in[3];
    const float* kw   = (const float*)d_in[4];
    const float* kb   = (const float*)d_in[5];
    const float* vw   = (const float*)d_in[6];
    const float* vb   = (const float*)d_in[7];
    const float* ow   = (const float*)d_in[8];
    const float* ob   = (const float*)d_in[9];
    float* out = (float*)d_out;

    static cudaStream_t s_aux = nullptr;
    static cudaEvent_t ev_fork = nullptr, ev_kv = nullptr, ev_join = nullptr;
    static int attr_done = 0;
    if (!attr_done) {
        cudaFuncSetAttribute(gemm_proj_kernel,  cudaFuncAttributeMaxDynamicSharedMemorySize, SMEM_BYTES);
        cudaFuncSetAttribute(gemm_hscan_kernel, cudaFuncAttributeMaxDynamicSharedMemorySize, SMEM_BYTES);
        cudaFuncSetAttribute(gemm_qk_kernel,    cudaFuncAttributeMaxDynamicSharedMemorySize, SMEM_BYTES);
        cudaFuncSetAttribute(gemm_out_kernel,   cudaFuncAttributeMaxDynamicSharedMemorySize, SMEM_BYTES);
        cudaFuncSetAttribute(gemm_oproj_kernel, cudaFuncAttributeMaxDynamicSharedMemorySize, SMEM_BYTES);
        cudaStreamCreateWithFlags(&s_aux, cudaStreamNonBlocking);
        cudaEventCreateWithFlags(&ev_fork, cudaEventDisableTiming);
        cudaEventCreateWithFlags(&ev_kv,   cudaEventDisableTiming);
        cudaEventCreateWithFlags(&ev_join, cudaEventDisableTiming);
        attr_done = 1;
    }

    // main: conversions
    conv_w_kernel<<<(int)(((size_t)4 * EE * EE + 255) / 256), 256>>>(qw, kw, vw, ow);
    conv_xT_kernel<<<dim3(TT / 32, EE / 32, BB), dim3(32, 8)>>>(x);

    // fork after conversions: aux does the q pipeline, main does k/v + hscan
    cudaEventRecord(ev_fork, 0);
    cudaStreamWaitEvent(s_aux, ev_fork, 0);

    // aux: q projection + softmax/split
    gemm_proj_kernel<<<dim3(BB * TT / 128, EE / 128, 1), 128, SMEM_BYTES, s_aux>>>(
        qb, kb, vb, toep, 0);
    act_kernel<<<BB * TT, 128, 0, s_aux>>>();

    // main: k/v projections, then state scan
    gemm_proj_kernel<<<dim3(BB * TT / 128, EE / 128, 2), 128, SMEM_BYTES>>>(
        qb, kb, vb, toep, 1);
    cudaEventRecord(ev_kv, 0);
    gemm_hscan_kernel<<<dim3(EE / 128, EE / 128, BB), 128, SMEM_BYTES>>>();

    // aux (needs k/v results): zprefix, qk, dz
    cudaStreamWaitEvent(s_aux, ev_kv, 0);
    zprefix_kernel<<<(BB * EE + 127) / 128, 128, 0, s_aux>>>();
    gemm_qk_kernel<<<BB * NCH, 128, SMEM_BYTES, s_aux>>>();
    dz_kernel<<<BB * NCH, 256, 0, s_aux>>>();
    cudaEventRecord(ev_join, s_aux);

    // main: join, then out + oproj
    cudaStreamWaitEvent(0, ev_join, 0);
    gemm_out_kernel<<<dim3(EE / 128, BB * NCH), 128, SMEM_BYTES>>>();
    gemm_oproj_kernel<<<dim3(BB * TT / 128, EE / 128), 128, SMEM_BYTES>>>(ob, out);
}